// round 8
// baseline (speedup 1.0000x reference)
#include <cuda_runtime.h>
#include <cuda_fp16.h>
#include <math.h>
#include <stdint.h>

// ---------------- problem constants ----------------
constexpr int kB = 16;
constexpr int kS = 512;
constexpr int kD = 512;
constexpr int kH = 8;
constexpr int kL = 6;
constexpr int kDFF = 2048;
constexpr int kVOCAB = 1024;
constexpr int kNPC = 4096;
constexpr int kNS = 4096;
constexpr int kM = kB * kS;  // 8192 rows
constexpr int kQKVN = 3 * kD; // 1536

// ---------------- scratch (static device globals; no allocations) ----------------
__device__ float  g_x[(size_t)kM * kD];        // residual stream (fp32)
__device__ __half g_xh[(size_t)kM * kD];       // half copy for GEMM input
__device__ __half g_qkvh[(size_t)kM * 1024];   // Q (0-511) and K (512-1023), half
__device__ __half g_vth[(size_t)kM * kD];      // V transposed: [b][h*64+d][s], half
__device__ __half g_atth[(size_t)kM * kD];     // attention output, half
__device__ float  g_t[(size_t)kM * kD];        // pre-LN branch (fp32)
__device__ __half g_ffh[(size_t)kM * kDFF];    // FFN hidden, half
__device__ float  g_bias[(size_t)kB * kS * kS];// dense relation bias (fp32)
__device__ __half g_wqkvh[(size_t)kL * kQKVN * kD];
__device__ float  g_bqkv[(size_t)kL * kQKVN];
__device__ __half g_woh[(size_t)kL * kD * kD];
__device__ __half g_w1h[(size_t)kL * kDFF * kD];
__device__ __half g_w2h[(size_t)kL * kD * kDFF];

// ---------------- mma / ldmatrix / cp.async helpers ----------------
__device__ __forceinline__ void mma16(float* c, const uint32_t* a, const uint32_t* b) {
    asm volatile(
        "mma.sync.aligned.m16n8k16.row.col.f32.f16.f16.f32 "
        "{%0,%1,%2,%3},{%4,%5,%6,%7},{%8,%9},{%0,%1,%2,%3};"
        : "+f"(c[0]), "+f"(c[1]), "+f"(c[2]), "+f"(c[3])
        : "r"(a[0]), "r"(a[1]), "r"(a[2]), "r"(a[3]), "r"(b[0]), "r"(b[1]));
}

__device__ __forceinline__ void ldsm_x4h(uint32_t* r, const __half* p) {
    uint32_t addr = (uint32_t)__cvta_generic_to_shared(p);
    asm volatile("ldmatrix.sync.aligned.m8n8.x4.shared.b16 {%0,%1,%2,%3}, [%4];"
        : "=r"(r[0]), "=r"(r[1]), "=r"(r[2]), "=r"(r[3]) : "r"(addr));
}

__device__ __forceinline__ void cpa16(void* smem_dst, const void* gsrc) {
    uint32_t sa = (uint32_t)__cvta_generic_to_shared(smem_dst);
    asm volatile("cp.async.cg.shared.global [%0], [%1], 16;" :: "r"(sa), "l"(gsrc) : "memory");
}
__device__ __forceinline__ void cpa_commit() {
    asm volatile("cp.async.commit_group;" ::: "memory");
}
__device__ __forceinline__ void cpa_wait0() {
    asm volatile("cp.async.wait_group 0;" ::: "memory");
}
__device__ __forceinline__ void cpa_wait1() {
    asm volatile("cp.async.wait_group 1;" ::: "memory");
}

// ---------------- prep kernels ----------------
__global__ __launch_bounds__(256) void prep_qkv_w(
    const float* __restrict__ Wq, const float* __restrict__ Wk,
    const float* __restrict__ Wv, __half* __restrict__ wout)
{
    size_t n = (size_t)kL * kQKVN * kD;
    for (size_t idx = (size_t)blockIdx.x * blockDim.x + threadIdx.x; idx < n;
         idx += (size_t)gridDim.x * blockDim.x) {
        size_t l = idx / ((size_t)kQKVN * kD);
        size_t rem = idx % ((size_t)kQKVN * kD);
        int r = (int)(rem / kD), c = (int)(rem % kD);
        float v;
        if (r < kD)            v = Wq[(l * kD + r) * kD + c];
        else if (r < 2 * kD)   v = Wk[(l * kD + (r - kD)) * kD + c];
        else                   v = Wv[(l * kD + (r - 2 * kD)) * kD + c];
        wout[idx] = __float2half_rn(v);
    }
}

__global__ __launch_bounds__(256) void prep_qkv_b(
    const float* __restrict__ bq, const float* __restrict__ bk,
    const float* __restrict__ bv, float* __restrict__ bout)
{
    int idx = blockIdx.x * blockDim.x + threadIdx.x;
    if (idx >= kL * kQKVN) return;
    int l = idx / kQKVN, r = idx % kQKVN;
    float v;
    if (r < kD)          v = bq[l * kD + r];
    else if (r < 2 * kD) v = bk[l * kD + (r - kD)];
    else                 v = bv[l * kD + (r - 2 * kD)];
    bout[idx] = v;
}

__global__ __launch_bounds__(256) void half_copy(
    const float* __restrict__ src, __half* __restrict__ dst, size_t n)
{
    for (size_t i = (size_t)blockIdx.x * blockDim.x + threadIdx.x; i < n;
         i += (size_t)gridDim.x * blockDim.x)
        dst[i] = __float2half_rn(src[i]);
}

// ---------------- dense relation-bias matrix ----------------
__global__ __launch_bounds__(256) void zero_bias(float* __restrict__ bias)
{
    size_t n = (size_t)kB * kS * kS;
    for (size_t i = (size_t)blockIdx.x * blockDim.x + threadIdx.x; i < n;
         i += (size_t)gridDim.x * blockDim.x)
        bias[i] = 0.0f;
}

__global__ __launch_bounds__(256) void scatter_pc(
    const int* __restrict__ pci, const float* __restrict__ rel, float* __restrict__ bias)
{
    int e = blockIdx.x * blockDim.x + threadIdx.x;
    if (e >= kNPC) return;
    int b = pci[e * 3 + 0], i = pci[e * 3 + 1], j = pci[e * 3 + 2];
    atomicAdd(&bias[((size_t)b * kS + i) * kS + j], rel[0]);
    atomicAdd(&bias[((size_t)b * kS + j) * kS + i], rel[1]);
}

__global__ __launch_bounds__(256) void scatter_sib(
    const int* __restrict__ sbi, const float* __restrict__ rel, float* __restrict__ bias)
{
    int e = blockIdx.x * blockDim.x + threadIdx.x;
    if (e >= kNS) return;
    int b = sbi[e * 3 + 0], i = sbi[e * 3 + 1], j = sbi[e * 3 + 2];
    float r2 = rel[2];
    atomicAdd(&bias[((size_t)b * kS + i) * kS + j], r2);
    atomicAdd(&bias[((size_t)b * kS + j) * kS + i], r2);
}

// ---------------- embedding + positional + degree ----------------
__global__ __launch_bounds__(128) void embed_kernel(
    const int* __restrict__ raw_x, const int* __restrict__ deg,
    const float* __restrict__ vemb, const float* __restrict__ demb,
    float* __restrict__ x)
{
    const int row = blockIdx.x;
    const int s = row & (kS - 1);
    const int tok = raw_x[row];
    const int dg = deg[row];
    const float c0 = -logf(10000.0f) / (float)kD;
    for (int c = threadIdx.x; c < kD; c += blockDim.x) {
        int p = c >> 1;
        float ang = (float)s * expf((float)(2 * p) * c0);
        float pe = (c & 1) ? cosf(ang) : sinf(ang);
        x[(size_t)row * kD + c] = vemb[(size_t)tok * kD + c] + pe + demb[(size_t)dg * kD + c];
    }
}

__global__ __launch_bounds__(256) void relnow_kernel(
    const int* __restrict__ pcn, const int* __restrict__ sn,
    const float* __restrict__ are, float* __restrict__ x)
{
    int idx = blockIdx.x * blockDim.x + threadIdx.x;
    if (idx >= kB * kD) return;
    int b = idx / kD, c = idx % kD;
    {
        int bb = pcn[b * 2 + 0], ss = pcn[b * 2 + 1];
        atomicAdd(&x[((size_t)bb * kS + ss) * kD + c], are[c]);
    }
    {
        int bb = sn[b * 2 + 0], ss = sn[b * 2 + 1];
        atomicAdd(&x[((size_t)bb * kS + ss) * kD + c], are[kD + c]);
    }
}

// ============================================================
// fp16 tensor-core GEMM, CTA tile 128x256, warp tile 64x64,
// 8 warps (2x4), BK=64 halfs, 3-stage cp.async, 1 CTA/SM.
// acc(fp32) = A[M,K](half) @ W[N,K]^T(half) + bias(fp32)
// MODE 0: fp32 out Cf.  MODE 1: half out Ch (+optional relu).
// MODE 2: QKV — Q,K tiles (n0<1024) to Ch stride 1024; V tiles
//         (n0>=1024) transposed into vt[b][hd][s] (half).
// ============================================================
constexpr int kStrideH = 72;                       // 64 + 8 pad (halfs)
constexpr int kAStageH = 128 * kStrideH;
constexpr int kBStageH = 256 * kStrideH;
constexpr int kStageH = kAStageH + kBStageH;       // 27,648 halfs / stage
constexpr int kGemmSmemBytes = 3 * kStageH * 2;    // 165,888 B

template <bool RELU, int MODE>
__global__ __launch_bounds__(256, 1) void gemm_fp16(
    const __half* __restrict__ A, const __half* __restrict__ W,
    const float* __restrict__ bias, float* __restrict__ Cf,
    __half* __restrict__ Ch, __half* __restrict__ vt,
    int M, int N, int K)
{
    extern __shared__ __half smh[];
    const int tid = threadIdx.x;
    const int lane = tid & 31, warp = tid >> 5;
    const int wm = warp >> 2, wn = warp & 3;           // 2 x 4 warp grid
    const int m0 = blockIdx.y << 7, n0 = blockIdx.x << 8;

    // fragment lane addressing (16-byte row blocks)
    const int a_row = (((lane >> 3) & 1) << 3) + (lane & 7);
    const int a_col = (lane >> 4) << 3;
    const int b_row = ((lane >> 4) << 3) + (lane & 7);
    const int b_col = ((lane >> 3) & 1) << 3;

    const int lr = tid >> 3;           // 0..31
    const int lc8 = (tid & 7) << 3;    // 0..56

    auto issue = [&](int ch, int st) {
        const __half* Ab = A + (size_t)m0 * K + (size_t)ch * 64 + lc8;
        const __half* Wb = W + (size_t)n0 * K + (size_t)ch * 64 + lc8;
        __half* Ad = smh + st * kStageH + lc8;
        __half* Bd = smh + st * kStageH + kAStageH + lc8;
#pragma unroll
        for (int it = 0; it < 4; it++) {
            int row = lr + (it << 5);
            cpa16(Ad + row * kStrideH, Ab + (size_t)row * K);
        }
#pragma unroll
        for (int it = 0; it < 8; it++) {
            int row = lr + (it << 5);
            cpa16(Bd + row * kStrideH, Wb + (size_t)row * K);
        }
        cpa_commit();
    };

    float acc[4][8][4] = {};
    const int nch = K >> 6;
    issue(0, 0);
    issue(1, 1);
    int st = 0, st2 = 2;
    for (int ch = 0; ch < nch; ch++) {
        if (ch + 1 < nch) cpa_wait1(); else cpa_wait0();
        __syncthreads();
        if (ch + 2 < nch) issue(ch + 2, st2);
        const __half* Ar = smh + st * kStageH;
        const __half* Br = Ar + kAStageH;
#pragma unroll
        for (int ks = 0; ks < 4; ks++) {
            int kc = ks << 4;
            uint32_t af[4][4], bp[4][4];
#pragma unroll
            for (int mt = 0; mt < 4; mt++)
                ldsm_x4h(af[mt], Ar + ((wm << 6) + (mt << 4) + a_row) * kStrideH + kc + a_col);
#pragma unroll
            for (int p = 0; p < 4; p++)
                ldsm_x4h(bp[p], Br + ((wn << 6) + (p << 4) + b_row) * kStrideH + kc + b_col);
#pragma unroll
            for (int mt = 0; mt < 4; mt++)
#pragma unroll
                for (int nt = 0; nt < 8; nt++)
                    mma16(acc[mt][nt], af[mt], &bp[nt >> 1][(nt & 1) << 1]);
        }
        st = (st == 2) ? 0 : st + 1;
        st2 = (st2 == 2) ? 0 : st2 + 1;
    }

    if (MODE == 2 && n0 >= 1024) {
        // V tile -> vt[b][hd][s] transposed (half)
        const int bidx = m0 >> 9;
        __half* vtb = vt + ((size_t)bidx << 9) * kS;
#pragma unroll
        for (int mt = 0; mt < 4; mt++) {
            int s = (m0 & 511) + (wm << 6) + (mt << 4) + (lane >> 2);
#pragma unroll
            for (int nt = 0; nt < 8; nt++) {
                int col = n0 + (wn << 6) + (nt << 3) + ((lane & 3) << 1);
                int hd = col - 1024;
                float bb0 = bias[col], bb1 = bias[col + 1];
                vtb[(size_t)hd * kS + s]           = __float2half_rn(acc[mt][nt][0] + bb0);
                vtb[(size_t)(hd + 1) * kS + s]     = __float2half_rn(acc[mt][nt][1] + bb1);
                vtb[(size_t)hd * kS + s + 8]       = __float2half_rn(acc[mt][nt][2] + bb0);
                vtb[(size_t)(hd + 1) * kS + s + 8] = __float2half_rn(acc[mt][nt][3] + bb1);
            }
        }
        return;
    }
#pragma unroll
    for (int mt = 0; mt < 4; mt++) {
        int row = m0 + (wm << 6) + (mt << 4) + (lane >> 2);
#pragma unroll
        for (int nt = 0; nt < 8; nt++) {
            int col = n0 + (wn << 6) + (nt << 3) + ((lane & 3) << 1);
            float bb0 = bias[col], bb1 = bias[col + 1];
            float v0 = acc[mt][nt][0] + bb0, v1 = acc[mt][nt][1] + bb1;
            float v2 = acc[mt][nt][2] + bb0, v3 = acc[mt][nt][3] + bb1;
            if (RELU) {
                v0 = fmaxf(v0, 0.0f); v1 = fmaxf(v1, 0.0f);
                v2 = fmaxf(v2, 0.0f); v3 = fmaxf(v3, 0.0f);
            }
            if (MODE == 0) {
                *(float2*)(Cf + (size_t)row * N + col) = make_float2(v0, v1);
                *(float2*)(Cf + (size_t)(row + 8) * N + col) = make_float2(v2, v3);
            } else if (MODE == 1) {
                *(__half2*)(Ch + (size_t)row * N + col) = __floats2half2_rn(v0, v1);
                *(__half2*)(Ch + (size_t)(row + 8) * N + col) = __floats2half2_rn(v2, v3);
            } else {
                // MODE 2, Q/K tile: stride 1024
                *(__half2*)(Ch + (size_t)row * 1024 + col) = __floats2half2_rn(v0, v1);
                *(__half2*)(Ch + (size_t)(row + 8) * 1024 + col) = __floats2half2_rn(v2, v3);
            }
        }
    }
}

// ============================================================
// Fused fp16 flash attention with additive dense fp32 bias.
// Q,K from qkvh [kM][1024]; V from vth [b][h*64+d][s].
// ============================================================
constexpr int kQsOff = 0;                        // [128][72]
constexpr int kKsOff = 128 * kStrideH;           // [64][72]
constexpr int kVsOff = kKsOff + 64 * kStrideH;   // [64][72]
constexpr int kPsOff = kVsOff + 64 * kStrideH;   // [128][72]
constexpr int kFlashSmemH = kPsOff + 128 * kStrideH;
constexpr int kFlashSmemBytes = kFlashSmemH * 2; // 55,296 B

__global__ __launch_bounds__(256, 2) void flash_attn(
    const __half* __restrict__ qkv, const __half* __restrict__ vt,
    const float* __restrict__ bias, __half* __restrict__ out)
{
    extern __shared__ __half smh[];
    __half* Qs = smh + kQsOff;
    __half* Ks = smh + kKsOff;
    __half* Vs = smh + kVsOff;
    __half* Ps = smh + kPsOff;
    const int bh = blockIdx.y;
    const int b = bh >> 3, h = bh & 7;
    const int i0 = blockIdx.x << 7;
    const int tid = threadIdx.x;
    const int lane = tid & 31, w = tid >> 5;
    const int quad = lane & 3;
    const int r0l = (w << 4) + (lane >> 2);
    const size_t rowbase = (size_t)b * kS;

    const int a_row = (((lane >> 3) & 1) << 3) + (lane & 7);
    const int a_col = (lane >> 4) << 3;
    const int b_row = ((lane >> 4) << 3) + (lane & 7);
    const int b_col = ((lane >> 3) & 1) << 3;

    // load Q tile (128 x 64 halfs)
    {
        const __half* Qg = qkv + (rowbase + i0) * 1024 + h * 64;
#pragma unroll
        for (int it = 0; it < 4; it++) {
            int u = tid + (it << 8);
            int row = u >> 3, c8 = (u & 7) << 3;
            cpa16(Qs + row * kStrideH + c8, Qg + (size_t)row * 1024 + c8);
        }
        cpa_commit();
    }

    float oacc[8][4] = {};
    float mh[2] = {-1e30f, -1e30f};
    float lh[2] = {0.0f, 0.0f};

    const __half* Vgb = vt + ((rowbase << 9) + (size_t)h * 64 * kS);

    for (int jt = 0; jt < 8; jt++) {
        const int j0 = jt << 6;
        {
            const __half* Kg = qkv + (rowbase + j0) * 1024 + 512 + h * 64;
#pragma unroll
            for (int it = 0; it < 2; it++) {
                int u = tid + (it << 8);
                int row = u >> 3, c8 = (u & 7) << 3;
                cpa16(Ks + row * kStrideH + c8, Kg + (size_t)row * 1024 + c8);
                cpa16(Vs + row * kStrideH + c8, Vgb + (size_t)row * kS + j0 + c8);
            }
            cpa_commit();
        }
        cpa_wait0();
        __syncthreads();

        // S = Q @ K^T   (warp: 16 rows x 64 j)
        float s[8][4] = {};
#pragma unroll
        for (int ks = 0; ks < 4; ks++) {
            int kc = ks << 4;
            uint32_t af[4], bp[4][4];
            ldsm_x4h(af, Qs + ((w << 4) + a_row) * kStrideH + kc + a_col);
#pragma unroll
            for (int p = 0; p < 4; p++)
                ldsm_x4h(bp[p], Ks + ((p << 4) + b_row) * kStrideH + kc + b_col);
#pragma unroll
            for (int nt = 0; nt < 8; nt++)
                mma16(s[nt], af, &bp[nt >> 1][(nt & 1) << 1]);
        }

        const size_t bi1 = (rowbase + i0 + r0l) * kS + j0;
        const size_t bi2 = (rowbase + i0 + r0l + 8) * kS + j0;
#pragma unroll
        for (int nt = 0; nt < 8; nt++) {
            int jc = (nt << 3) + (quad << 1);
            float2 z1 = *(const float2*)(bias + bi1 + jc);
            float2 z2 = *(const float2*)(bias + bi2 + jc);
            s[nt][0] = s[nt][0] * 0.125f + z1.x;
            s[nt][1] = s[nt][1] * 0.125f + z1.y;
            s[nt][2] = s[nt][2] * 0.125f + z2.x;
            s[nt][3] = s[nt][3] * 0.125f + z2.y;
        }
        float mx0 = -1e30f, mx1 = -1e30f;
#pragma unroll
        for (int nt = 0; nt < 8; nt++) {
            mx0 = fmaxf(mx0, fmaxf(s[nt][0], s[nt][1]));
            mx1 = fmaxf(mx1, fmaxf(s[nt][2], s[nt][3]));
        }
        mx0 = fmaxf(mx0, __shfl_xor_sync(0xffffffffu, mx0, 1));
        mx0 = fmaxf(mx0, __shfl_xor_sync(0xffffffffu, mx0, 2));
        mx1 = fmaxf(mx1, __shfl_xor_sync(0xffffffffu, mx1, 1));
        mx1 = fmaxf(mx1, __shfl_xor_sync(0xffffffffu, mx1, 2));
        float mn0 = fmaxf(mh[0], mx0), mn1 = fmaxf(mh[1], mx1);
        float sc0 = __expf(mh[0] - mn0), sc1 = __expf(mh[1] - mn1);
        mh[0] = mn0; mh[1] = mn1;
        float ps0 = 0.0f, ps1 = 0.0f;
#pragma unroll
        for (int nt = 0; nt < 8; nt++) {
            __half2 h1 = __floats2half2_rn(__expf(s[nt][0] - mn0), __expf(s[nt][1] - mn0));
            __half2 h2 = __floats2half2_rn(__expf(s[nt][2] - mn1), __expf(s[nt][3] - mn1));
            float2 f1 = __half22float2(h1);
            float2 f2 = __half22float2(h2);
            ps0 += f1.x + f1.y; ps1 += f2.x + f2.y;
            int jc = (nt << 3) + (quad << 1);
            *(__half2*)(Ps + r0l * kStrideH + jc) = h1;
            *(__half2*)(Ps + (r0l + 8) * kStrideH + jc) = h2;
        }
        ps0 += __shfl_xor_sync(0xffffffffu, ps0, 1);
        ps0 += __shfl_xor_sync(0xffffffffu, ps0, 2);
        ps1 += __shfl_xor_sync(0xffffffffu, ps1, 1);
        ps1 += __shfl_xor_sync(0xffffffffu, ps1, 2);
        lh[0] = lh[0] * sc0 + ps0;
        lh[1] = lh[1] * sc1 + ps1;
#pragma unroll
        for (int dt = 0; dt < 8; dt++) {
            oacc[dt][0] *= sc0; oacc[dt][1] *= sc0;
            oacc[dt][2] *= sc1; oacc[dt][3] *= sc1;
        }
        __syncwarp();

        // O += P @ V   (A = warp-local P rows; B = V^T rows d)
#pragma unroll
        for (int ks = 0; ks < 4; ks++) {
            int kc = ks << 4;
            uint32_t af[4], bp[4][4];
            ldsm_x4h(af, Ps + ((w << 4) + a_row) * kStrideH + kc + a_col);
#pragma unroll
            for (int p = 0; p < 4; p++)
                ldsm_x4h(bp[p], Vs + ((p << 4) + b_row) * kStrideH + kc + b_col);
#pragma unroll
            for (int dt = 0; dt < 8; dt++)
                mma16(oacc[dt], af, &bp[dt >> 1][(dt & 1) << 1]);
        }
        __syncthreads();   // Ks/Vs consumed by all warps before next load
    }

    float inv0 = 1.0f / lh[0], inv1 = 1.0f / lh[1];
    __half* o1 = out + (rowbase + i0 + r0l) * kD + h * 64;
    __half* o2 = out + (rowbase + i0 + r0l + 8) * kD + h * 64;
#pragma unroll
    for (int dt = 0; dt < 8; dt++) {
        int dc = (dt << 3) + (quad << 1);
        *(__half2*)(o1 + dc) = __floats2half2_rn(oacc[dt][0] * inv0, oacc[dt][1] * inv0);
        *(__half2*)(o2 + dc) = __floats2half2_rn(oacc[dt][2] * inv1, oacc[dt][3] * inv1);
    }
}

// ---------------- LN(a + r): writes fp32 + half copies ----------------
__global__ __launch_bounds__(256) void ln_residual_dual(
    const float* __restrict__ a, const float* __restrict__ r,
    const float* __restrict__ g, const float* __restrict__ bet,
    float* __restrict__ outf, __half* __restrict__ outh)
{
    const size_t row = (size_t)blockIdx.x * 8 + (threadIdx.x >> 5);
    const int lane = threadIdx.x & 31;
    const float* ap = a + row * kD;
    const float* rp = r + row * kD;
    float v[16];
    float sum = 0.0f;
#pragma unroll
    for (int t = 0; t < 16; t++) {
        v[t] = ap[lane + t * 32] + rp[lane + t * 32];
        sum += v[t];
    }
#pragma unroll
    for (int s = 16; s; s >>= 1) sum += __shfl_xor_sync(0xffffffffu, sum, s);
    float mean = sum * (1.0f / kD);
    float s2 = 0.0f;
#pragma unroll
    for (int t = 0; t < 16; t++) { float d = v[t] - mean; s2 += d * d; }
#pragma unroll
    for (int s = 16; s; s >>= 1) s2 += __shfl_xor_sync(0xffffffffu, s2, s);
    float rstd = rsqrtf(s2 * (1.0f / kD) + 1e-5f);
#pragma unroll
    for (int t = 0; t < 16; t++) {
        int c = lane + t * 32;
        float o = (v[t] - mean) * rstd * g[c] + bet[c];
        outf[row * kD + c] = o;
        outh[row * kD + c] = __float2half_rn(o);
    }
}

// ---------------- final logits (fp32) ----------------
__global__ __launch_bounds__(256) void logits_kernel(
    const float* __restrict__ x, const float* __restrict__ w,
    float* __restrict__ out)
{
    int gw = (blockIdx.x * blockDim.x + threadIdx.x) >> 5;
    int lane = threadIdx.x & 31;
    if (gw >= kB * kVOCAB) return;
    int b = gw >> 10;
    int vcb = gw & (kVOCAB - 1);
    const float* xr = x + ((size_t)b * kS + (kS - 1)) * kD;
    const float* wr = w + (size_t)vcb * kD;
    float s = 0.0f;
#pragma unroll
    for (int t = 0; t < 16; t++) s += xr[lane + t * 32] * wr[lane + t * 32];
#pragma unroll
    for (int sh = 16; sh; sh >>= 1) s += __shfl_xor_sync(0xffffffffu, s, sh);
    if (lane == 0) out[gw] = s;
}

// ---------------- host launcher ----------------
extern "C" void kernel_launch(void* const* d_in, const int* in_sizes, int n_in,
                              void* d_out, int out_size)
{
    (void)in_sizes; (void)n_in; (void)out_size;
    const int*   raw_x = (const int*)d_in[0];
    const int*   deg   = (const int*)d_in[1];
    const int*   pci   = (const int*)d_in[2];
    const int*   pcn   = (const int*)d_in[3];
    const int*   sbi   = (const int*)d_in[4];
    const int*   sbn   = (const int*)d_in[5];
    const float* vemb  = (const float*)d_in[6];
    const float* demb  = (const float*)d_in[7];
    const float* are   = (const float*)d_in[8];
    const float* rel   = (const float*)d_in[9];
    const float* Wq    = (const float*)d_in[10];
    const float* bq    = (const float*)d_in[11];
    const float* Wk    = (const float*)d_in[12];
    const float* bk    = (const float*)d_in[13];
    const float* Wv    = (const float*)d_in[14];
    const float* bv    = (const float*)d_in[15];
    const float* Wo    = (const float*)d_in[16];
    const float* bo    = (const float*)d_in[17];
    const float* W1    = (const float*)d_in[18];
    const float* b1    = (const float*)d_in[19];
    const float* W2    = (const float*)d_in[20];
    const float* b2    = (const float*)d_in[21];
    const float* lng   = (const float*)d_in[22];
    const float* lnb   = (const float*)d_in[23];
    const float* logw  = (const float*)d_in[24];
    float* out = (float*)d_out;

    float *x, *t, *bias, *bqkv;
    __half *xh, *qkvh, *vth, *atth, *ffh, *wqkvh, *woh, *w1h, *w2h;
    cudaGetSymbolAddress((void**)&x,     g_x);
    cudaGetSymbolAddress((void**)&xh,    g_xh);
    cudaGetSymbolAddress((void**)&qkvh,  g_qkvh);
    cudaGetSymbolAddress((void**)&vth,   g_vth);
    cudaGetSymbolAddress((void**)&atth,  g_atth);
    cudaGetSymbolAddress((void**)&t,     g_t);
    cudaGetSymbolAddress((void**)&ffh,   g_ffh);
    cudaGetSymbolAddress((void**)&bias,  g_bias);
    cudaGetSymbolAddress((void**)&wqkvh, g_wqkvh);
    cudaGetSymbolAddress((void**)&bqkv,  g_bqkv);
    cudaGetSymbolAddress((void**)&woh,   g_woh);
    cudaGetSymbolAddress((void**)&w1h,   g_w1h);
    cudaGetSymbolAddress((void**)&w2h,   g_w2h);

    cudaFuncSetAttribute(gemm_fp16<false, 2>, cudaFuncAttributeMaxDynamicSharedMemorySize, kGemmSmemBytes);
    cudaFuncSetAttribute(gemm_fp16<false, 0>, cudaFuncAttributeMaxDynamicSharedMemorySize, kGemmSmemBytes);
    cudaFuncSetAttribute(gemm_fp16<true, 1>,  cudaFuncAttributeMaxDynamicSharedMemorySize, kGemmSmemBytes);
    cudaFuncSetAttribute(flash_attn,          cudaFuncAttributeMaxDynamicSharedMemorySize, kFlashSmemBytes);

    // ---- prep ----
    prep_qkv_w<<<2048, 256>>>(Wq, Wk, Wv, wqkvh);
    prep_qkv_b<<<(kL * kQKVN + 255) / 256, 256>>>(bq, bk, bv, bqkv);
    half_copy<<<2048, 256>>>(Wo, woh, (size_t)kL * kD * kD);
    half_copy<<<2048, 256>>>(W1, w1h, (size_t)kL * kDFF * kD);
    half_copy<<<2048, 256>>>(W2, w2h, (size_t)kL * kD * kDFF);
    zero_bias<<<2048, 256>>>(bias);
    scatter_pc<<<(kNPC + 255) / 256, 256>>>(pci, rel, bias);
    scatter_sib<<<(kNS + 255) / 256, 256>>>(sbi, rel, bias);

    embed_kernel<<<kM, 128>>>(raw_x, deg, vemb, demb, x);
    relnow_kernel<<<(kB * kD + 255) / 256, 256>>>(pcn, sbn, are, x);
    half_copy<<<2048, 256>>>(x, xh, (size_t)kM * kD);

    const dim3 gQKV(kQKVN / 256, kM / 128);  // (6, 64)
    const dim3 gD(kD / 256, kM / 128);       // (2, 64)
    const dim3 gFF(kDFF / 256, kM / 128);    // (8, 64)
    const dim3 gFl(kS / 128, kB * kH);       // (4, 128)

    for (int l = 0; l < kL; l++) {
        const __half* wqkvl = wqkvh + (size_t)l * kQKVN * kD;
        const float*  bqkvl = bqkv + (size_t)l * kQKVN;
        const __half* wol = woh + (size_t)l * kD * kD;
        const __half* w1l = w1h + (size_t)l * kDFF * kD;
        const __half* w2l = w2h + (size_t)l * kD * kDFF;
        const float* bol = bo + (size_t)l * kD;
        const float* b1l = b1 + (size_t)l * kDFF;
        const float* b2l = b2 + (size_t)l * kD;
        const float* lngl = lng + (size_t)l * kD;
        const float* lnbl = lnb + (size_t)l * kD;

        gemm_fp16<false, 2><<<gQKV, 256, kGemmSmemBytes>>>(
            xh, wqkvl, bqkvl, nullptr, qkvh, vth, kM, kQKVN, kD);
        flash_attn<<<gFl, 256, kFlashSmemBytes>>>(qkvh, vth, bias, atth);
        gemm_fp16<false, 0><<<gD, 256, kGemmSmemBytes>>>(
            atth, wol, bol, t, nullptr, nullptr, kM, kD, kD);
        ln_residual_dual<<<kM / 8, 256>>>(x, t, lngl, lnbl, x, xh);

        gemm_fp16<true, 1><<<gFF, 256, kGemmSmemBytes>>>(
            xh, w1l, b1l, nullptr, ffh, nullptr, kM, kDFF, kD);
        gemm_fp16<false, 0><<<gD, 256, kGemmSmemBytes>>>(
            ffh, w2l, b2l, t, nullptr, nullptr, kM, kD, kDFF);
        ln_residual_dual<<<kM / 8, 256>>>(x, t, lngl, lnbl, x, xh);
    }

    logits_kernel<<<(kB * kVOCAB * 32 + 255) / 256, 256>>>(x, logw, out);
}

// round 9
// speedup vs baseline: 1.0587x; 1.0587x over previous
#include <cuda_runtime.h>
#include <cuda_fp16.h>
#include <math.h>
#include <stdint.h>

// ---------------- problem constants ----------------
constexpr int kB = 16;
constexpr int kS = 512;
constexpr int kD = 512;
constexpr int kH = 8;
constexpr int kL = 6;
constexpr int kDFF = 2048;
constexpr int kVOCAB = 1024;
constexpr int kNPC = 4096;
constexpr int kNS = 4096;
constexpr int kM = kB * kS;  // 8192 rows
constexpr int kQKVN = 3 * kD; // 1536

// ---------------- scratch (static device globals; no allocations) ----------------
__device__ float  g_x[(size_t)kM * kD];        // residual stream (fp32)
__device__ __half g_xh[(size_t)kM * kD];       // half copy for GEMM input
__device__ __half g_qkvh[(size_t)kM * 1024];   // Q (0-511) and K (512-1023), half
__device__ __half g_vth[(size_t)kM * kD];      // V transposed: [b][h*64+d][s], half
__device__ __half g_atth[(size_t)kM * kD];     // attention output, half
__device__ __half g_th[(size_t)kM * kD];       // pre-LN branch (half)
__device__ __half g_ffh[(size_t)kM * kDFF];    // FFN hidden, half
__device__ float  g_bias[(size_t)kB * kS * kS];// dense relation bias (fp32)
__device__ __half g_wqkvh[(size_t)kL * kQKVN * kD];
__device__ float  g_bqkv[(size_t)kL * kQKVN];
__device__ __half g_woh[(size_t)kL * kD * kD];
__device__ __half g_w1h[(size_t)kL * kDFF * kD];
__device__ __half g_w2h[(size_t)kL * kD * kDFF];

// ---------------- mma / ldmatrix / cp.async helpers ----------------
__device__ __forceinline__ void mma16(float* c, const uint32_t* a, const uint32_t* b) {
    asm volatile(
        "mma.sync.aligned.m16n8k16.row.col.f32.f16.f16.f32 "
        "{%0,%1,%2,%3},{%4,%5,%6,%7},{%8,%9},{%0,%1,%2,%3};"
        : "+f"(c[0]), "+f"(c[1]), "+f"(c[2]), "+f"(c[3])
        : "r"(a[0]), "r"(a[1]), "r"(a[2]), "r"(a[3]), "r"(b[0]), "r"(b[1]));
}

__device__ __forceinline__ void ldsm_x4h(uint32_t* r, const __half* p) {
    uint32_t addr = (uint32_t)__cvta_generic_to_shared(p);
    asm volatile("ldmatrix.sync.aligned.m8n8.x4.shared.b16 {%0,%1,%2,%3}, [%4];"
        : "=r"(r[0]), "=r"(r[1]), "=r"(r[2]), "=r"(r[3]) : "r"(addr));
}

__device__ __forceinline__ void cpa16(void* smem_dst, const void* gsrc) {
    uint32_t sa = (uint32_t)__cvta_generic_to_shared(smem_dst);
    asm volatile("cp.async.cg.shared.global [%0], [%1], 16;" :: "r"(sa), "l"(gsrc) : "memory");
}
__device__ __forceinline__ void cpa_commit() {
    asm volatile("cp.async.commit_group;" ::: "memory");
}
__device__ __forceinline__ void cpa_wait0() {
    asm volatile("cp.async.wait_group 0;" ::: "memory");
}
__device__ __forceinline__ void cpa_wait1() {
    asm volatile("cp.async.wait_group 1;" ::: "memory");
}

// ---------------- prep kernels ----------------
__global__ __launch_bounds__(256) void prep_qkv_w(
    const float* __restrict__ Wq, const float* __restrict__ Wk,
    const float* __restrict__ Wv, __half* __restrict__ wout)
{
    size_t n = (size_t)kL * kQKVN * kD;
    for (size_t idx = (size_t)blockIdx.x * blockDim.x + threadIdx.x; idx < n;
         idx += (size_t)gridDim.x * blockDim.x) {
        size_t l = idx / ((size_t)kQKVN * kD);
        size_t rem = idx % ((size_t)kQKVN * kD);
        int r = (int)(rem / kD), c = (int)(rem % kD);
        float v;
        if (r < kD)            v = Wq[(l * kD + r) * kD + c];
        else if (r < 2 * kD)   v = Wk[(l * kD + (r - kD)) * kD + c];
        else                   v = Wv[(l * kD + (r - 2 * kD)) * kD + c];
        wout[idx] = __float2half_rn(v);
    }
}

__global__ __launch_bounds__(256) void prep_qkv_b(
    const float* __restrict__ bq, const float* __restrict__ bk,
    const float* __restrict__ bv, float* __restrict__ bout)
{
    int idx = blockIdx.x * blockDim.x + threadIdx.x;
    if (idx >= kL * kQKVN) return;
    int l = idx / kQKVN, r = idx % kQKVN;
    float v;
    if (r < kD)          v = bq[l * kD + r];
    else if (r < 2 * kD) v = bk[l * kD + (r - kD)];
    else                 v = bv[l * kD + (r - 2 * kD)];
    bout[idx] = v;
}

__global__ __launch_bounds__(256) void half_copy(
    const float* __restrict__ src, __half* __restrict__ dst, size_t n)
{
    for (size_t i = (size_t)blockIdx.x * blockDim.x + threadIdx.x; i < n;
         i += (size_t)gridDim.x * blockDim.x)
        dst[i] = __float2half_rn(src[i]);
}

// ---------------- dense relation-bias matrix ----------------
__global__ __launch_bounds__(256) void zero_bias(float* __restrict__ bias)
{
    size_t n = (size_t)kB * kS * kS;
    for (size_t i = (size_t)blockIdx.x * blockDim.x + threadIdx.x; i < n;
         i += (size_t)gridDim.x * blockDim.x)
        bias[i] = 0.0f;
}

__global__ __launch_bounds__(256) void scatter_pc(
    const int* __restrict__ pci, const float* __restrict__ rel, float* __restrict__ bias)
{
    int e = blockIdx.x * blockDim.x + threadIdx.x;
    if (e >= kNPC) return;
    int b = pci[e * 3 + 0], i = pci[e * 3 + 1], j = pci[e * 3 + 2];
    atomicAdd(&bias[((size_t)b * kS + i) * kS + j], rel[0]);
    atomicAdd(&bias[((size_t)b * kS + j) * kS + i], rel[1]);
}

__global__ __launch_bounds__(256) void scatter_sib(
    const int* __restrict__ sbi, const float* __restrict__ rel, float* __restrict__ bias)
{
    int e = blockIdx.x * blockDim.x + threadIdx.x;
    if (e >= kNS) return;
    int b = sbi[e * 3 + 0], i = sbi[e * 3 + 1], j = sbi[e * 3 + 2];
    float r2 = rel[2];
    atomicAdd(&bias[((size_t)b * kS + i) * kS + j], r2);
    atomicAdd(&bias[((size_t)b * kS + j) * kS + i], r2);
}

// ---------------- embedding + positional + degree ----------------
__global__ __launch_bounds__(128) void embed_kernel(
    const int* __restrict__ raw_x, const int* __restrict__ deg,
    const float* __restrict__ vemb, const float* __restrict__ demb,
    float* __restrict__ x)
{
    const int row = blockIdx.x;
    const int s = row & (kS - 1);
    const int tok = raw_x[row];
    const int dg = deg[row];
    const float c0 = -logf(10000.0f) / (float)kD;
    for (int c = threadIdx.x; c < kD; c += blockDim.x) {
        int p = c >> 1;
        float ang = (float)s * expf((float)(2 * p) * c0);
        float pe = (c & 1) ? cosf(ang) : sinf(ang);
        x[(size_t)row * kD + c] = vemb[(size_t)tok * kD + c] + pe + demb[(size_t)dg * kD + c];
    }
}

__global__ __launch_bounds__(256) void relnow_kernel(
    const int* __restrict__ pcn, const int* __restrict__ sn,
    const float* __restrict__ are, float* __restrict__ x)
{
    int idx = blockIdx.x * blockDim.x + threadIdx.x;
    if (idx >= kB * kD) return;
    int b = idx / kD, c = idx % kD;
    {
        int bb = pcn[b * 2 + 0], ss = pcn[b * 2 + 1];
        atomicAdd(&x[((size_t)bb * kS + ss) * kD + c], are[c]);
    }
    {
        int bb = sn[b * 2 + 0], ss = sn[b * 2 + 1];
        atomicAdd(&x[((size_t)bb * kS + ss) * kD + c], are[kD + c]);
    }
}

// ============================================================
// fp16 tensor-core GEMM, 3-stage cp.async pipeline (R7 config).
// acc(fp32) = A[M,K](half) @ W[N,K]^T(half) + bias(fp32)
// MODE 0: half out Ch (no relu).  MODE 1: half out Ch + relu.
// MODE 2: QKV — Q,K tiles (n0<1024) to Ch stride 1024; V tiles
//         (n0>=1024) transposed into vt[b][hd][s] (half).
// 128x128 tile, 8 warps (64x32), BK=64 halfs, smem stride 72.
// ============================================================
constexpr int kStrideH = 72;
constexpr int kStageH = 2 * 128 * kStrideH;            // halfs per stage (A+B)
constexpr int kGemmSmemBytes = 3 * kStageH * 2;        // 110,592 B

template <bool RELU, int MODE>
__global__ __launch_bounds__(256, 2) void gemm_fp16(
    const __half* __restrict__ A, const __half* __restrict__ W,
    const float* __restrict__ bias, __half* __restrict__ Ch,
    __half* __restrict__ vt, int M, int N, int K)
{
    extern __shared__ __half smh[];
    const int tid = threadIdx.x;
    const int lane = tid & 31, warp = tid >> 5;
    const int wm = warp >> 2, wn = warp & 3;
    const int m0 = blockIdx.y << 7, n0 = blockIdx.x << 7;

    // fragment lane addressing
    const int a_row = (((lane >> 3) & 1) << 3) + (lane & 7);
    const int a_col = (lane >> 4) << 3;
    const int b_row = ((lane >> 4) << 3) + (lane & 7);
    const int b_col = ((lane >> 3) & 1) << 3;

    auto issue = [&](int ch, int st) {
        const __half* Ab = A + (size_t)m0 * K + (size_t)ch * 64;
        const __half* Wb = W + (size_t)n0 * K + (size_t)ch * 64;
        __half* Ad = smh + st * kStageH;
        __half* Bd = Ad + (kStageH >> 1);
#pragma unroll
        for (int it = 0; it < 4; it++) {
            int u = tid + (it << 8);       // 0..1023
            int row = u >> 3, c8 = (u & 7) << 3;
            cpa16(Ad + row * kStrideH + c8, Ab + (size_t)row * K + c8);
            cpa16(Bd + row * kStrideH + c8, Wb + (size_t)row * K + c8);
        }
        cpa_commit();
    };

    float acc[4][4][4] = {};
    const int nch = K >> 6;
    issue(0, 0);
    issue(1, 1);
    int st = 0, st2 = 2;
    for (int ch = 0; ch < nch; ch++) {
        if (ch + 1 < nch) cpa_wait1(); else cpa_wait0();
        __syncthreads();
        if (ch + 2 < nch) issue(ch + 2, st2);
        const __half* Ar = smh + st * kStageH;
        const __half* Br = Ar + (kStageH >> 1);
#pragma unroll
        for (int ks = 0; ks < 4; ks++) {
            int kc = ks << 4;
            uint32_t af[4][4], bp[2][4];
#pragma unroll
            for (int mt = 0; mt < 4; mt++)
                ldsm_x4h(af[mt], Ar + ((wm << 6) + (mt << 4) + a_row) * kStrideH + kc + a_col);
#pragma unroll
            for (int p = 0; p < 2; p++)
                ldsm_x4h(bp[p], Br + ((wn << 5) + (p << 4) + b_row) * kStrideH + kc + b_col);
#pragma unroll
            for (int mt = 0; mt < 4; mt++)
#pragma unroll
                for (int nt = 0; nt < 4; nt++)
                    mma16(acc[mt][nt], af[mt], &bp[nt >> 1][(nt & 1) << 1]);
        }
        st = (st == 2) ? 0 : st + 1;
        st2 = (st2 == 2) ? 0 : st2 + 1;
    }

    if (MODE == 2 && n0 >= 1024) {
        // V tile -> vt[b][hd][s] transposed (half)
        const int bidx = m0 >> 9;
        __half* vtb = vt + ((size_t)bidx << 9) * kS;
#pragma unroll
        for (int mt = 0; mt < 4; mt++) {
            int s = (m0 & 511) + (wm << 6) + (mt << 4) + (lane >> 2);
#pragma unroll
            for (int nt = 0; nt < 4; nt++) {
                int col = n0 + (wn << 5) + (nt << 3) + ((lane & 3) << 1);
                int hd = col - 1024;
                float bb0 = bias[col], bb1 = bias[col + 1];
                vtb[(size_t)hd * kS + s]           = __float2half_rn(acc[mt][nt][0] + bb0);
                vtb[(size_t)(hd + 1) * kS + s]     = __float2half_rn(acc[mt][nt][1] + bb1);
                vtb[(size_t)hd * kS + s + 8]       = __float2half_rn(acc[mt][nt][2] + bb0);
                vtb[(size_t)(hd + 1) * kS + s + 8] = __float2half_rn(acc[mt][nt][3] + bb1);
            }
        }
        return;
    }
#pragma unroll
    for (int mt = 0; mt < 4; mt++) {
        int row = m0 + (wm << 6) + (mt << 4) + (lane >> 2);
#pragma unroll
        for (int nt = 0; nt < 4; nt++) {
            int col = n0 + (wn << 5) + (nt << 3) + ((lane & 3) << 1);
            float bb0 = bias[col], bb1 = bias[col + 1];
            float v0 = acc[mt][nt][0] + bb0, v1 = acc[mt][nt][1] + bb1;
            float v2 = acc[mt][nt][2] + bb0, v3 = acc[mt][nt][3] + bb1;
            if (RELU) {
                v0 = fmaxf(v0, 0.0f); v1 = fmaxf(v1, 0.0f);
                v2 = fmaxf(v2, 0.0f); v3 = fmaxf(v3, 0.0f);
            }
            if (MODE == 2) {
                // Q/K tile: stride 1024
                *(__half2*)(Ch + (size_t)row * 1024 + col) = __floats2half2_rn(v0, v1);
                *(__half2*)(Ch + (size_t)(row + 8) * 1024 + col) = __floats2half2_rn(v2, v3);
            } else {
                *(__half2*)(Ch + (size_t)row * N + col) = __floats2half2_rn(v0, v1);
                *(__half2*)(Ch + (size_t)(row + 8) * N + col) = __floats2half2_rn(v2, v3);
            }
        }
    }
}

// ============================================================
// Fused fp16 flash attention with additive dense fp32 bias.
// Q,K from qkvh [kM][1024]; V from vth [b][h*64+d][s].
// ============================================================
constexpr int kQsOff = 0;                        // [128][72]
constexpr int kKsOff = 128 * kStrideH;           // [64][72]
constexpr int kVsOff = kKsOff + 64 * kStrideH;   // [64][72]
constexpr int kPsOff = kVsOff + 64 * kStrideH;   // [128][72]
constexpr int kFlashSmemH = kPsOff + 128 * kStrideH;
constexpr int kFlashSmemBytes = kFlashSmemH * 2; // 55,296 B

__global__ __launch_bounds__(256, 2) void flash_attn(
    const __half* __restrict__ qkv, const __half* __restrict__ vt,
    const float* __restrict__ bias, __half* __restrict__ out)
{
    extern __shared__ __half smh[];
    __half* Qs = smh + kQsOff;
    __half* Ks = smh + kKsOff;
    __half* Vs = smh + kVsOff;
    __half* Ps = smh + kPsOff;
    const int bh = blockIdx.y;
    const int b = bh >> 3, h = bh & 7;
    const int i0 = blockIdx.x << 7;
    const int tid = threadIdx.x;
    const int lane = tid & 31, w = tid >> 5;
    const int quad = lane & 3;
    const int r0l = (w << 4) + (lane >> 2);
    const size_t rowbase = (size_t)b * kS;

    const int a_row = (((lane >> 3) & 1) << 3) + (lane & 7);
    const int a_col = (lane >> 4) << 3;
    const int b_row = ((lane >> 4) << 3) + (lane & 7);
    const int b_col = ((lane >> 3) & 1) << 3;

    // load Q tile (128 x 64 halfs)
    {
        const __half* Qg = qkv + (rowbase + i0) * 1024 + h * 64;
#pragma unroll
        for (int it = 0; it < 4; it++) {
            int u = tid + (it << 8);
            int row = u >> 3, c8 = (u & 7) << 3;
            cpa16(Qs + row * kStrideH + c8, Qg + (size_t)row * 1024 + c8);
        }
        cpa_commit();
    }

    float oacc[8][4] = {};
    float mh[2] = {-1e30f, -1e30f};
    float lh[2] = {0.0f, 0.0f};

    const __half* Vgb = vt + ((rowbase << 9) + (size_t)h * 64 * kS);

    for (int jt = 0; jt < 8; jt++) {
        const int j0 = jt << 6;
        {
            const __half* Kg = qkv + (rowbase + j0) * 1024 + 512 + h * 64;
#pragma unroll
            for (int it = 0; it < 2; it++) {
                int u = tid + (it << 8);
                int row = u >> 3, c8 = (u & 7) << 3;
                cpa16(Ks + row * kStrideH + c8, Kg + (size_t)row * 1024 + c8);
                cpa16(Vs + row * kStrideH + c8, Vgb + (size_t)row * kS + j0 + c8);
            }
            cpa_commit();
        }
        cpa_wait0();
        __syncthreads();

        // S = Q @ K^T   (warp: 16 rows x 64 j)
        float s[8][4] = {};
#pragma unroll
        for (int ks = 0; ks < 4; ks++) {
            int kc = ks << 4;
            uint32_t af[4], bp[4][4];
            ldsm_x4h(af, Qs + ((w << 4) + a_row) * kStrideH + kc + a_col);
#pragma unroll
            for (int p = 0; p < 4; p++)
                ldsm_x4h(bp[p], Ks + ((p << 4) + b_row) * kStrideH + kc + b_col);
#pragma unroll
            for (int nt = 0; nt < 8; nt++)
                mma16(s[nt], af, &bp[nt >> 1][(nt & 1) << 1]);
        }

        const size_t bi1 = (rowbase + i0 + r0l) * kS + j0;
        const size_t bi2 = (rowbase + i0 + r0l + 8) * kS + j0;
#pragma unroll
        for (int nt = 0; nt < 8; nt++) {
            int jc = (nt << 3) + (quad << 1);
            float2 z1 = *(const float2*)(bias + bi1 + jc);
            float2 z2 = *(const float2*)(bias + bi2 + jc);
            s[nt][0] = s[nt][0] * 0.125f + z1.x;
            s[nt][1] = s[nt][1] * 0.125f + z1.y;
            s[nt][2] = s[nt][2] * 0.125f + z2.x;
            s[nt][3] = s[nt][3] * 0.125f + z2.y;
        }
        float mx0 = -1e30f, mx1 = -1e30f;
#pragma unroll
        for (int nt = 0; nt < 8; nt++) {
            mx0 = fmaxf(mx0, fmaxf(s[nt][0], s[nt][1]));
            mx1 = fmaxf(mx1, fmaxf(s[nt][2], s[nt][3]));
        }
        mx0 = fmaxf(mx0, __shfl_xor_sync(0xffffffffu, mx0, 1));
        mx0 = fmaxf(mx0, __shfl_xor_sync(0xffffffffu, mx0, 2));
        mx1 = fmaxf(mx1, __shfl_xor_sync(0xffffffffu, mx1, 1));
        mx1 = fmaxf(mx1, __shfl_xor_sync(0xffffffffu, mx1, 2));
        float mn0 = fmaxf(mh[0], mx0), mn1 = fmaxf(mh[1], mx1);
        float sc0 = __expf(mh[0] - mn0), sc1 = __expf(mh[1] - mn1);
        mh[0] = mn0; mh[1] = mn1;
        float ps0 = 0.0f, ps1 = 0.0f;
#pragma unroll
        for (int nt = 0; nt < 8; nt++) {
            __half2 h1 = __floats2half2_rn(__expf(s[nt][0] - mn0), __expf(s[nt][1] - mn0));
            __half2 h2 = __floats2half2_rn(__expf(s[nt][2] - mn1), __expf(s[nt][3] - mn1));
            float2 f1 = __half22float2(h1);
            float2 f2 = __half22float2(h2);
            ps0 += f1.x + f1.y; ps1 += f2.x + f2.y;
            int jc = (nt << 3) + (quad << 1);
            *(__half2*)(Ps + r0l * kStrideH + jc) = h1;
            *(__half2*)(Ps + (r0l + 8) * kStrideH + jc) = h2;
        }
        ps0 += __shfl_xor_sync(0xffffffffu, ps0, 1);
        ps0 += __shfl_xor_sync(0xffffffffu, ps0, 2);
        ps1 += __shfl_xor_sync(0xffffffffu, ps1, 1);
        ps1 += __shfl_xor_sync(0xffffffffu, ps1, 2);
        lh[0] = lh[0] * sc0 + ps0;
        lh[1] = lh[1] * sc1 + ps1;
#pragma unroll
        for (int dt = 0; dt < 8; dt++) {
            oacc[dt][0] *= sc0; oacc[dt][1] *= sc0;
            oacc[dt][2] *= sc1; oacc[dt][3] *= sc1;
        }
        __syncwarp();

        // O += P @ V   (A = warp-local P rows; B = V^T rows d)
#pragma unroll
        for (int ks = 0; ks < 4; ks++) {
            int kc = ks << 4;
            uint32_t af[4], bp[4][4];
            ldsm_x4h(af, Ps + ((w << 4) + a_row) * kStrideH + kc + a_col);
#pragma unroll
            for (int p = 0; p < 4; p++)
                ldsm_x4h(bp[p], Vs + ((p << 4) + b_row) * kStrideH + kc + b_col);
#pragma unroll
            for (int dt = 0; dt < 8; dt++)
                mma16(oacc[dt], af, &bp[dt >> 1][(dt & 1) << 1]);
        }
        __syncthreads();   // Ks/Vs consumed by all warps before next load
    }

    float inv0 = 1.0f / lh[0], inv1 = 1.0f / lh[1];
    __half* o1 = out + (rowbase + i0 + r0l) * kD + h * 64;
    __half* o2 = out + (rowbase + i0 + r0l + 8) * kD + h * 64;
#pragma unroll
    for (int dt = 0; dt < 8; dt++) {
        int dc = (dt << 3) + (quad << 1);
        *(__half2*)(o1 + dc) = __floats2half2_rn(oacc[dt][0] * inv0, oacc[dt][1] * inv0);
        *(__half2*)(o2 + dc) = __floats2half2_rn(oacc[dt][2] * inv1, oacc[dt][3] * inv1);
    }
}

// ---------------- LN(x + t_half): writes fp32 + half copies ----------------
__global__ __launch_bounds__(256) void ln_residual_dual(
    const float* __restrict__ a, const __half* __restrict__ r,
    const float* __restrict__ g, const float* __restrict__ bet,
    float* __restrict__ outf, __half* __restrict__ outh)
{
    const size_t row = (size_t)blockIdx.x * 8 + (threadIdx.x >> 5);
    const int lane = threadIdx.x & 31;
    const float* ap = a + row * kD;
    const __half* rp = r + row * kD;
    float v[16];
    float sum = 0.0f;
#pragma unroll
    for (int t = 0; t < 8; t++) {
        int c = (lane << 1) + (t << 6);
        float2 a2 = *(const float2*)(ap + c);
        float2 r2 = __half22float2(*(const __half2*)(rp + c));
        v[2 * t] = a2.x + r2.x;
        v[2 * t + 1] = a2.y + r2.y;
        sum += v[2 * t] + v[2 * t + 1];
    }
#pragma unroll
    for (int s = 16; s; s >>= 1) sum += __shfl_xor_sync(0xffffffffu, sum, s);
    float mean = sum * (1.0f / kD);
    float s2 = 0.0f;
#pragma unroll
    for (int t = 0; t < 16; t++) { float d = v[t] - mean; s2 += d * d; }
#pragma unroll
    for (int s = 16; s; s >>= 1) s2 += __shfl_xor_sync(0xffffffffu, s2, s);
    float rstd = rsqrtf(s2 * (1.0f / kD) + 1e-5f);
#pragma unroll
    for (int t = 0; t < 8; t++) {
        int c = (lane << 1) + (t << 6);
        float o0 = (v[2 * t] - mean) * rstd * g[c] + bet[c];
        float o1 = (v[2 * t + 1] - mean) * rstd * g[c + 1] + bet[c + 1];
        *(float2*)(outf + row * kD + c) = make_float2(o0, o1);
        *(__half2*)(outh + row * kD + c) = __floats2half2_rn(o0, o1);
    }
}

// ---------------- final logits (fp32) ----------------
__global__ __launch_bounds__(256) void logits_kernel(
    const float* __restrict__ x, const float* __restrict__ w,
    float* __restrict__ out)
{
    int gw = (blockIdx.x * blockDim.x + threadIdx.x) >> 5;
    int lane = threadIdx.x & 31;
    if (gw >= kB * kVOCAB) return;
    int b = gw >> 10;
    int vcb = gw & (kVOCAB - 1);
    const float* xr = x + ((size_t)b * kS + (kS - 1)) * kD;
    const float* wr = w + (size_t)vcb * kD;
    float s = 0.0f;
#pragma unroll
    for (int t = 0; t < 16; t++) s += xr[lane + t * 32] * wr[lane + t * 32];
#pragma unroll
    for (int sh = 16; sh; sh >>= 1) s += __shfl_xor_sync(0xffffffffu, s, sh);
    if (lane == 0) out[gw] = s;
}

// ---------------- host launcher ----------------
extern "C" void kernel_launch(void* const* d_in, const int* in_sizes, int n_in,
                              void* d_out, int out_size)
{
    (void)in_sizes; (void)n_in; (void)out_size;
    const int*   raw_x = (const int*)d_in[0];
    const int*   deg   = (const int*)d_in[1];
    const int*   pci   = (const int*)d_in[2];
    const int*   pcn   = (const int*)d_in[3];
    const int*   sbi   = (const int*)d_in[4];
    const int*   sbn   = (const int*)d_in[5];
    const float* vemb  = (const float*)d_in[6];
    const float* demb  = (const float*)d_in[7];
    const float* are   = (const float*)d_in[8];
    const float* rel   = (const float*)d_in[9];
    const float* Wq    = (const float*)d_in[10];
    const float* bq    = (const float*)d_in[11];
    const float* Wk    = (const float*)d_in[12];
    const float* bk    = (const float*)d_in[13];
    const float* Wv    = (const float*)d_in[14];
    const float* bv    = (const float*)d_in[15];
    const float* Wo    = (const float*)d_in[16];
    const float* bo    = (const float*)d_in[17];
    const float* W1    = (const float*)d_in[18];
    const float* b1    = (const float*)d_in[19];
    const float* W2    = (const float*)d_in[20];
    const float* b2    = (const float*)d_in[21];
    const float* lng   = (const float*)d_in[22];
    const float* lnb   = (const float*)d_in[23];
    const float* logw  = (const float*)d_in[24];
    float* out = (float*)d_out;

    float *x, *bias, *bqkv;
    __half *xh, *qkvh, *vth, *atth, *th, *ffh, *wqkvh, *woh, *w1h, *w2h;
    cudaGetSymbolAddress((void**)&x,     g_x);
    cudaGetSymbolAddress((void**)&xh,    g_xh);
    cudaGetSymbolAddress((void**)&qkvh,  g_qkvh);
    cudaGetSymbolAddress((void**)&vth,   g_vth);
    cudaGetSymbolAddress((void**)&atth,  g_atth);
    cudaGetSymbolAddress((void**)&th,    g_th);
    cudaGetSymbolAddress((void**)&ffh,   g_ffh);
    cudaGetSymbolAddress((void**)&bias,  g_bias);
    cudaGetSymbolAddress((void**)&wqkvh, g_wqkvh);
    cudaGetSymbolAddress((void**)&bqkv,  g_bqkv);
    cudaGetSymbolAddress((void**)&woh,   g_woh);
    cudaGetSymbolAddress((void**)&w1h,   g_w1h);
    cudaGetSymbolAddress((void**)&w2h,   g_w2h);

    cudaFuncSetAttribute(gemm_fp16<false, 2>, cudaFuncAttributeMaxDynamicSharedMemorySize, kGemmSmemBytes);
    cudaFuncSetAttribute(gemm_fp16<false, 0>, cudaFuncAttributeMaxDynamicSharedMemorySize, kGemmSmemBytes);
    cudaFuncSetAttribute(gemm_fp16<true, 1>,  cudaFuncAttributeMaxDynamicSharedMemorySize, kGemmSmemBytes);
    cudaFuncSetAttribute(flash_attn,          cudaFuncAttributeMaxDynamicSharedMemorySize, kFlashSmemBytes);

    const dim3 gQKV(kQKVN / 128, kM / 128);  // (12, 64)
    const dim3 gD(kD / 128, kM / 128);       // (4, 64)
    const dim3 gFF(kDFF / 128, kM / 128);    // (16, 64)
    const dim3 gFl(kS / 128, kB * kH);       // (4, 128)

    // ---- launch order arranged so launch index 5 is the layer-0 QKV GEMM
    //      (ncu -s 5 -c 1 then captures gemm_fp16 instead of a prep kernel) ----
    embed_kernel<<<kM, 128>>>(raw_x, deg, vemb, demb, x);                 // 0
    relnow_kernel<<<(kB * kD + 255) / 256, 256>>>(pcn, sbn, are, x);      // 1
    half_copy<<<2048, 256>>>(x, xh, (size_t)kM * kD);                     // 2
    prep_qkv_w<<<2048, 256>>>(Wq, Wk, Wv, wqkvh);                         // 3
    prep_qkv_b<<<(kL * kQKVN + 255) / 256, 256>>>(bq, bk, bv, bqkv);      // 4
    gemm_fp16<false, 2><<<gQKV, 256, kGemmSmemBytes>>>(                   // 5 (profiled)
        xh, wqkvh, bqkv, qkvh, vth, kM, kQKVN, kD);

    half_copy<<<2048, 256>>>(Wo, woh, (size_t)kL * kD * kD);
    half_copy<<<2048, 256>>>(W1, w1h, (size_t)kL * kDFF * kD);
    half_copy<<<2048, 256>>>(W2, w2h, (size_t)kL * kD * kDFF);
    zero_bias<<<2048, 256>>>(bias);
    scatter_pc<<<(kNPC + 255) / 256, 256>>>(pci, rel, bias);
    scatter_sib<<<(kNS + 255) / 256, 256>>>(sbi, rel, bias);

    for (int l = 0; l < kL; l++) {
        const __half* wqkvl = wqkvh + (size_t)l * kQKVN * kD;
        const float*  bqkvl = bqkv + (size_t)l * kQKVN;
        const __half* wol = woh + (size_t)l * kD * kD;
        const __half* w1l = w1h + (size_t)l * kDFF * kD;
        const __half* w2l = w2h + (size_t)l * kD * kDFF;
        const float* bol = bo + (size_t)l * kD;
        const float* b1l = b1 + (size_t)l * kDFF;
        const float* b2l = b2 + (size_t)l * kD;
        const float* lngl = lng + (size_t)l * kD;
        const float* lnbl = lnb + (size_t)l * kD;

        if (l > 0) {
            gemm_fp16<false, 2><<<gQKV, 256, kGemmSmemBytes>>>(
                xh, wqkvl, bqkvl, qkvh, vth, kM, kQKVN, kD);
        }
        flash_attn<<<gFl, 256, kFlashSmemBytes>>>(qkvh, vth, bias, atth);
        gemm_fp16<false, 0><<<gD, 256, kGemmSmemBytes>>>(
            atth, wol, bol, th, nullptr, kM, kD, kD);
        ln_residual_dual<<<kM / 8, 256>>>(x, th, lngl, lnbl, x, xh);

        gemm_fp16<true, 1><<<gFF, 256, kGemmSmemBytes>>>(
            xh, w1l, b1l, ffh, nullptr, kM, kDFF, kD);
        gemm_fp16<false, 0><<<gD, 256, kGemmSmemBytes>>>(
            ffh, w2l, b2l, th, nullptr, kM, kD, kDFF);
        ln_residual_dual<<<kM / 8, 256>>>(x, th, lngl, lnbl, x, xh);
    }

    logits_kernel<<<(kB * kVOCAB * 32 + 255) / 256, 256>>>(x, logw, out);
}

// round 10
// speedup vs baseline: 1.0671x; 1.0079x over previous
#include <cuda_runtime.h>
#include <cuda_fp16.h>
#include <math.h>
#include <stdint.h>

// ---------------- problem constants ----------------
constexpr int kB = 16;
constexpr int kS = 512;
constexpr int kD = 512;
constexpr int kH = 8;
constexpr int kL = 6;
constexpr int kDFF = 2048;
constexpr int kVOCAB = 1024;
constexpr int kNPC = 4096;
constexpr int kNS = 4096;
constexpr int kM = kB * kS;  // 8192 rows
constexpr int kQKVN = 3 * kD; // 1536

// ---------------- scratch (static device globals; no allocations) ----------------
__device__ float  g_x[(size_t)kM * kD];        // residual stream (fp32)
__device__ __half g_xh[(size_t)kM * kD];       // half copy for GEMM input
__device__ __half g_qkvh[(size_t)kM * 1024];   // Q (0-511) and K (512-1023), half
__device__ __half g_vth[(size_t)kM * kD];      // V transposed: [b][h*64+d][s], half
__device__ __half g_atth[(size_t)kM * kD];     // attention output, half
__device__ __half g_th[(size_t)kM * kD];       // pre-LN branch (half)
__device__ __half g_ffh[(size_t)kM * kDFF];    // FFN hidden, half
__device__ float  g_bias[(size_t)kB * kS * kS];// dense relation bias (fp32, scatter target)
__device__ __half g_biash[(size_t)kB * kS * kS];// dense relation bias (half, flash reads)
__device__ __half g_wqkvh[(size_t)kL * kQKVN * kD];
__device__ float  g_bqkv[(size_t)kL * kQKVN];
__device__ __half g_woh[(size_t)kL * kD * kD];
__device__ __half g_w1h[(size_t)kL * kDFF * kD];
__device__ __half g_w2h[(size_t)kL * kD * kDFF];

// ---------------- mma / ldmatrix / cp.async helpers ----------------
__device__ __forceinline__ void mma16(float* c, const uint32_t* a, const uint32_t* b) {
    asm volatile(
        "mma.sync.aligned.m16n8k16.row.col.f32.f16.f16.f32 "
        "{%0,%1,%2,%3},{%4,%5,%6,%7},{%8,%9},{%0,%1,%2,%3};"
        : "+f"(c[0]), "+f"(c[1]), "+f"(c[2]), "+f"(c[3])
        : "r"(a[0]), "r"(a[1]), "r"(a[2]), "r"(a[3]), "r"(b[0]), "r"(b[1]));
}

__device__ __forceinline__ void ldsm_x4h(uint32_t* r, const __half* p) {
    uint32_t addr = (uint32_t)__cvta_generic_to_shared(p);
    asm volatile("ldmatrix.sync.aligned.m8n8.x4.shared.b16 {%0,%1,%2,%3}, [%4];"
        : "=r"(r[0]), "=r"(r[1]), "=r"(r[2]), "=r"(r[3]) : "r"(addr));
}

__device__ __forceinline__ void cpa16(void* smem_dst, const void* gsrc) {
    uint32_t sa = (uint32_t)__cvta_generic_to_shared(smem_dst);
    asm volatile("cp.async.cg.shared.global [%0], [%1], 16;" :: "r"(sa), "l"(gsrc) : "memory");
}
__device__ __forceinline__ void cpa_commit() {
    asm volatile("cp.async.commit_group;" ::: "memory");
}
__device__ __forceinline__ void cpa_wait0() {
    asm volatile("cp.async.wait_group 0;" ::: "memory");
}
__device__ __forceinline__ void cpa_wait1() {
    asm volatile("cp.async.wait_group 1;" ::: "memory");
}

// ---------------- prep kernels ----------------
__global__ __launch_bounds__(256) void prep_qkv_w(
    const float* __restrict__ Wq, const float* __restrict__ Wk,
    const float* __restrict__ Wv, __half* __restrict__ wout)
{
    size_t n = (size_t)kL * kQKVN * kD;
    for (size_t idx = (size_t)blockIdx.x * blockDim.x + threadIdx.x; idx < n;
         idx += (size_t)gridDim.x * blockDim.x) {
        size_t l = idx / ((size_t)kQKVN * kD);
        size_t rem = idx % ((size_t)kQKVN * kD);
        int r = (int)(rem / kD), c = (int)(rem % kD);
        float v;
        if (r < kD)            v = Wq[(l * kD + r) * kD + c];
        else if (r < 2 * kD)   v = Wk[(l * kD + (r - kD)) * kD + c];
        else                   v = Wv[(l * kD + (r - 2 * kD)) * kD + c];
        wout[idx] = __float2half_rn(v);
    }
}

__global__ __launch_bounds__(256) void prep_qkv_b(
    const float* __restrict__ bq, const float* __restrict__ bk,
    const float* __restrict__ bv, float* __restrict__ bout)
{
    int idx = blockIdx.x * blockDim.x + threadIdx.x;
    if (idx >= kL * kQKVN) return;
    int l = idx / kQKVN, r = idx % kQKVN;
    float v;
    if (r < kD)          v = bq[l * kD + r];
    else if (r < 2 * kD) v = bk[l * kD + (r - kD)];
    else                 v = bv[l * kD + (r - 2 * kD)];
    bout[idx] = v;
}

__global__ __launch_bounds__(256) void half_copy(
    const float* __restrict__ src, __half* __restrict__ dst, size_t n)
{
    for (size_t i = (size_t)blockIdx.x * blockDim.x + threadIdx.x; i < n;
         i += (size_t)gridDim.x * blockDim.x)
        dst[i] = __float2half_rn(src[i]);
}

// ---------------- dense relation-bias matrix ----------------
__global__ __launch_bounds__(256) void zero_bias(float* __restrict__ bias)
{
    size_t n = (size_t)kB * kS * kS;
    for (size_t i = (size_t)blockIdx.x * blockDim.x + threadIdx.x; i < n;
         i += (size_t)gridDim.x * blockDim.x)
        bias[i] = 0.0f;
}

__global__ __launch_bounds__(256) void scatter_pc(
    const int* __restrict__ pci, const float* __restrict__ rel, float* __restrict__ bias)
{
    int e = blockIdx.x * blockDim.x + threadIdx.x;
    if (e >= kNPC) return;
    int b = pci[e * 3 + 0], i = pci[e * 3 + 1], j = pci[e * 3 + 2];
    atomicAdd(&bias[((size_t)b * kS + i) * kS + j], rel[0]);
    atomicAdd(&bias[((size_t)b * kS + j) * kS + i], rel[1]);
}

__global__ __launch_bounds__(256) void scatter_sib(
    const int* __restrict__ sbi, const float* __restrict__ rel, float* __restrict__ bias)
{
    int e = blockIdx.x * blockDim.x + threadIdx.x;
    if (e >= kNS) return;
    int b = sbi[e * 3 + 0], i = sbi[e * 3 + 1], j = sbi[e * 3 + 2];
    float r2 = rel[2];
    atomicAdd(&bias[((size_t)b * kS + i) * kS + j], r2);
    atomicAdd(&bias[((size_t)b * kS + j) * kS + i], r2);
}

// ---------------- embedding + positional + degree ----------------
__global__ __launch_bounds__(128) void embed_kernel(
    const int* __restrict__ raw_x, const int* __restrict__ deg,
    const float* __restrict__ vemb, const float* __restrict__ demb,
    float* __restrict__ x)
{
    const int row = blockIdx.x;
    const int s = row & (kS - 1);
    const int tok = raw_x[row];
    const int dg = deg[row];
    const float c0 = -logf(10000.0f) / (float)kD;
    for (int c = threadIdx.x; c < kD; c += blockDim.x) {
        int p = c >> 1;
        float ang = (float)s * expf((float)(2 * p) * c0);
        float pe = (c & 1) ? cosf(ang) : sinf(ang);
        x[(size_t)row * kD + c] = vemb[(size_t)tok * kD + c] + pe + demb[(size_t)dg * kD + c];
    }
}

__global__ __launch_bounds__(256) void relnow_kernel(
    const int* __restrict__ pcn, const int* __restrict__ sn,
    const float* __restrict__ are, float* __restrict__ x)
{
    int idx = blockIdx.x * blockDim.x + threadIdx.x;
    if (idx >= kB * kD) return;
    int b = idx / kD, c = idx % kD;
    {
        int bb = pcn[b * 2 + 0], ss = pcn[b * 2 + 1];
        atomicAdd(&x[((size_t)bb * kS + ss) * kD + c], are[c]);
    }
    {
        int bb = sn[b * 2 + 0], ss = sn[b * 2 + 1];
        atomicAdd(&x[((size_t)bb * kS + ss) * kD + c], are[kD + c]);
    }
}

// ============================================================
// fp16 tensor-core GEMM, 3-stage cp.async pipeline.
// acc(fp32) = A[M,K](half) @ W[N,K]^T(half) + bias(fp32)
// MODE 0: half out Ch (no relu).  MODE 1: half out Ch + relu.
// MODE 2: QKV — Q,K tiles (n0<1024) to Ch stride 1024; V tiles
//         (n0>=1024) transposed into vt[b][hd][s] (half).
// 128x128 tile, 8 warps (64x32), BK=64 halfs, smem stride 72.
// ============================================================
constexpr int kStrideH = 72;
constexpr int kStageH = 2 * 128 * kStrideH;            // halfs per stage (A+B)
constexpr int kGemmSmemBytes = 3 * kStageH * 2;        // 110,592 B

template <bool RELU, int MODE>
__global__ __launch_bounds__(256, 2) void gemm_fp16(
    const __half* __restrict__ A, const __half* __restrict__ W,
    const float* __restrict__ bias, __half* __restrict__ Ch,
    __half* __restrict__ vt, int M, int N, int K)
{
    extern __shared__ __half smh[];
    const int tid = threadIdx.x;
    const int lane = tid & 31, warp = tid >> 5;
    const int wm = warp >> 2, wn = warp & 3;
    const int m0 = blockIdx.y << 7, n0 = blockIdx.x << 7;

    // fragment lane addressing
    const int a_row = (((lane >> 3) & 1) << 3) + (lane & 7);
    const int a_col = (lane >> 4) << 3;
    const int b_row = ((lane >> 4) << 3) + (lane & 7);
    const int b_col = ((lane >> 3) & 1) << 3;

    auto issue = [&](int ch, int st) {
        const __half* Ab = A + (size_t)m0 * K + (size_t)ch * 64;
        const __half* Wb = W + (size_t)n0 * K + (size_t)ch * 64;
        __half* Ad = smh + st * kStageH;
        __half* Bd = Ad + (kStageH >> 1);
#pragma unroll
        for (int it = 0; it < 4; it++) {
            int u = tid + (it << 8);       // 0..1023
            int row = u >> 3, c8 = (u & 7) << 3;
            cpa16(Ad + row * kStrideH + c8, Ab + (size_t)row * K + c8);
            cpa16(Bd + row * kStrideH + c8, Wb + (size_t)row * K + c8);
        }
        cpa_commit();
    };

    float acc[4][4][4] = {};
    const int nch = K >> 6;
    issue(0, 0);
    issue(1, 1);
    int st = 0, st2 = 2;
    for (int ch = 0; ch < nch; ch++) {
        if (ch + 1 < nch) cpa_wait1(); else cpa_wait0();
        __syncthreads();
        if (ch + 2 < nch) issue(ch + 2, st2);
        const __half* Ar = smh + st * kStageH;
        const __half* Br = Ar + (kStageH >> 1);
#pragma unroll
        for (int ks = 0; ks < 4; ks++) {
            int kc = ks << 4;
            uint32_t af[4][4], bp[2][4];
#pragma unroll
            for (int mt = 0; mt < 4; mt++)
                ldsm_x4h(af[mt], Ar + ((wm << 6) + (mt << 4) + a_row) * kStrideH + kc + a_col);
#pragma unroll
            for (int p = 0; p < 2; p++)
                ldsm_x4h(bp[p], Br + ((wn << 5) + (p << 4) + b_row) * kStrideH + kc + b_col);
#pragma unroll
            for (int mt = 0; mt < 4; mt++)
#pragma unroll
                for (int nt = 0; nt < 4; nt++)
                    mma16(acc[mt][nt], af[mt], &bp[nt >> 1][(nt & 1) << 1]);
        }
        st = (st == 2) ? 0 : st + 1;
        st2 = (st2 == 2) ? 0 : st2 + 1;
    }

    if (MODE == 2 && n0 >= 1024) {
        // V tile -> vt[b][hd][s] transposed (half)
        const int bidx = m0 >> 9;
        __half* vtb = vt + ((size_t)bidx << 9) * kS;
#pragma unroll
        for (int mt = 0; mt < 4; mt++) {
            int s = (m0 & 511) + (wm << 6) + (mt << 4) + (lane >> 2);
#pragma unroll
            for (int nt = 0; nt < 4; nt++) {
                int col = n0 + (wn << 5) + (nt << 3) + ((lane & 3) << 1);
                int hd = col - 1024;
                float bb0 = bias[col], bb1 = bias[col + 1];
                vtb[(size_t)hd * kS + s]           = __float2half_rn(acc[mt][nt][0] + bb0);
                vtb[(size_t)(hd + 1) * kS + s]     = __float2half_rn(acc[mt][nt][1] + bb1);
                vtb[(size_t)hd * kS + s + 8]       = __float2half_rn(acc[mt][nt][2] + bb0);
                vtb[(size_t)(hd + 1) * kS + s + 8] = __float2half_rn(acc[mt][nt][3] + bb1);
            }
        }
        return;
    }
#pragma unroll
    for (int mt = 0; mt < 4; mt++) {
        int row = m0 + (wm << 6) + (mt << 4) + (lane >> 2);
#pragma unroll
        for (int nt = 0; nt < 4; nt++) {
            int col = n0 + (wn << 5) + (nt << 3) + ((lane & 3) << 1);
            float bb0 = bias[col], bb1 = bias[col + 1];
            float v0 = acc[mt][nt][0] + bb0, v1 = acc[mt][nt][1] + bb1;
            float v2 = acc[mt][nt][2] + bb0, v3 = acc[mt][nt][3] + bb1;
            if (RELU) {
                v0 = fmaxf(v0, 0.0f); v1 = fmaxf(v1, 0.0f);
                v2 = fmaxf(v2, 0.0f); v3 = fmaxf(v3, 0.0f);
            }
            if (MODE == 2) {
                // Q/K tile: stride 1024
                *(__half2*)(Ch + (size_t)row * 1024 + col) = __floats2half2_rn(v0, v1);
                *(__half2*)(Ch + (size_t)(row + 8) * 1024 + col) = __floats2half2_rn(v2, v3);
            } else {
                *(__half2*)(Ch + (size_t)row * N + col) = __floats2half2_rn(v0, v1);
                *(__half2*)(Ch + (size_t)(row + 8) * N + col) = __floats2half2_rn(v2, v3);
            }
        }
    }
}

// ============================================================
// Fused fp16 flash attention, double-buffered K/V, half bias.
// Q,K from qkvh [kM][1024]; V from vth [b][h*64+d][s].
// ============================================================
constexpr int kQsOff = 0;                         // [128][72]
constexpr int kKsOff = 128 * kStrideH;            // [2][64][72]
constexpr int kVsOff = kKsOff + 2 * 64 * kStrideH;// [2][64][72]
constexpr int kPsOff = kVsOff + 2 * 64 * kStrideH;// [128][72]
constexpr int kFlashSmemH = kPsOff + 128 * kStrideH;
constexpr int kFlashSmemBytes = kFlashSmemH * 2;  // 73,728 B

__global__ __launch_bounds__(256, 2) void flash_attn(
    const __half* __restrict__ qkv, const __half* __restrict__ vt,
    const __half* __restrict__ bias, __half* __restrict__ out)
{
    extern __shared__ __half smh[];
    __half* Qs = smh + kQsOff;
    __half* Ps = smh + kPsOff;
    const int bh = blockIdx.y;
    const int b = bh >> 3, h = bh & 7;
    const int i0 = blockIdx.x << 7;
    const int tid = threadIdx.x;
    const int lane = tid & 31, w = tid >> 5;
    const int quad = lane & 3;
    const int r0l = (w << 4) + (lane >> 2);
    const size_t rowbase = (size_t)b * kS;

    const int a_row = (((lane >> 3) & 1) << 3) + (lane & 7);
    const int a_col = (lane >> 4) << 3;
    const int b_row = ((lane >> 4) << 3) + (lane & 7);
    const int b_col = ((lane >> 3) & 1) << 3;

    const __half* Vgb = vt + ((rowbase << 9) + (size_t)h * 64 * kS);

    auto issueKV = [&](int jt, int buf) {
        const int j0 = jt << 6;
        __half* Ks = smh + kKsOff + buf * 64 * kStrideH;
        __half* Vs = smh + kVsOff + buf * 64 * kStrideH;
        const __half* Kg = qkv + (rowbase + j0) * 1024 + 512 + h * 64;
#pragma unroll
        for (int it = 0; it < 2; it++) {
            int u = tid + (it << 8);
            int row = u >> 3, c8 = (u & 7) << 3;
            cpa16(Ks + row * kStrideH + c8, Kg + (size_t)row * 1024 + c8);
            cpa16(Vs + row * kStrideH + c8, Vgb + (size_t)row * kS + j0 + c8);
        }
        cpa_commit();
    };

    // load Q tile (128 x 64 halfs), then first K/V
    {
        const __half* Qg = qkv + (rowbase + i0) * 1024 + h * 64;
#pragma unroll
        for (int it = 0; it < 4; it++) {
            int u = tid + (it << 8);
            int row = u >> 3, c8 = (u & 7) << 3;
            cpa16(Qs + row * kStrideH + c8, Qg + (size_t)row * 1024 + c8);
        }
        cpa_commit();
    }
    issueKV(0, 0);

    float oacc[8][4] = {};
    float mh[2] = {-1e30f, -1e30f};
    float lh[2] = {0.0f, 0.0f};

    for (int jt = 0; jt < 8; jt++) {
        const int j0 = jt << 6;
        const int buf = jt & 1;
        if (jt + 1 < 8) { issueKV(jt + 1, buf ^ 1); cpa_wait1(); }
        else            { cpa_wait0(); }
        __syncthreads();
        const __half* Ks = smh + kKsOff + buf * 64 * kStrideH;
        const __half* Vs = smh + kVsOff + buf * 64 * kStrideH;

        // S = Q @ K^T   (warp: 16 rows x 64 j)
        float s[8][4] = {};
#pragma unroll
        for (int ks = 0; ks < 4; ks++) {
            int kc = ks << 4;
            uint32_t af[4], bp[4][4];
            ldsm_x4h(af, Qs + ((w << 4) + a_row) * kStrideH + kc + a_col);
#pragma unroll
            for (int p = 0; p < 4; p++)
                ldsm_x4h(bp[p], Ks + ((p << 4) + b_row) * kStrideH + kc + b_col);
#pragma unroll
            for (int nt = 0; nt < 8; nt++)
                mma16(s[nt], af, &bp[nt >> 1][(nt & 1) << 1]);
        }

        const size_t bi1 = (rowbase + i0 + r0l) * kS + j0;
        const size_t bi2 = (rowbase + i0 + r0l + 8) * kS + j0;
#pragma unroll
        for (int nt = 0; nt < 8; nt++) {
            int jc = (nt << 3) + (quad << 1);
            float2 z1 = __half22float2(*(const __half2*)(bias + bi1 + jc));
            float2 z2 = __half22float2(*(const __half2*)(bias + bi2 + jc));
            s[nt][0] = s[nt][0] * 0.125f + z1.x;
            s[nt][1] = s[nt][1] * 0.125f + z1.y;
            s[nt][2] = s[nt][2] * 0.125f + z2.x;
            s[nt][3] = s[nt][3] * 0.125f + z2.y;
        }
        float mx0 = -1e30f, mx1 = -1e30f;
#pragma unroll
        for (int nt = 0; nt < 8; nt++) {
            mx0 = fmaxf(mx0, fmaxf(s[nt][0], s[nt][1]));
            mx1 = fmaxf(mx1, fmaxf(s[nt][2], s[nt][3]));
        }
        mx0 = fmaxf(mx0, __shfl_xor_sync(0xffffffffu, mx0, 1));
        mx0 = fmaxf(mx0, __shfl_xor_sync(0xffffffffu, mx0, 2));
        mx1 = fmaxf(mx1, __shfl_xor_sync(0xffffffffu, mx1, 1));
        mx1 = fmaxf(mx1, __shfl_xor_sync(0xffffffffu, mx1, 2));
        float mn0 = fmaxf(mh[0], mx0), mn1 = fmaxf(mh[1], mx1);
        float sc0 = __expf(mh[0] - mn0), sc1 = __expf(mh[1] - mn1);
        mh[0] = mn0; mh[1] = mn1;
        float ps0 = 0.0f, ps1 = 0.0f;
#pragma unroll
        for (int nt = 0; nt < 8; nt++) {
            __half2 h1 = __floats2half2_rn(__expf(s[nt][0] - mn0), __expf(s[nt][1] - mn0));
            __half2 h2 = __floats2half2_rn(__expf(s[nt][2] - mn1), __expf(s[nt][3] - mn1));
            float2 f1 = __half22float2(h1);
            float2 f2 = __half22float2(h2);
            ps0 += f1.x + f1.y; ps1 += f2.x + f2.y;
            int jc = (nt << 3) + (quad << 1);
            *(__half2*)(Ps + r0l * kStrideH + jc) = h1;
            *(__half2*)(Ps + (r0l + 8) * kStrideH + jc) = h2;
        }
        ps0 += __shfl_xor_sync(0xffffffffu, ps0, 1);
        ps0 += __shfl_xor_sync(0xffffffffu, ps0, 2);
        ps1 += __shfl_xor_sync(0xffffffffu, ps1, 1);
        ps1 += __shfl_xor_sync(0xffffffffu, ps1, 2);
        lh[0] = lh[0] * sc0 + ps0;
        lh[1] = lh[1] * sc1 + ps1;
#pragma unroll
        for (int dt = 0; dt < 8; dt++) {
            oacc[dt][0] *= sc0; oacc[dt][1] *= sc0;
            oacc[dt][2] *= sc1; oacc[dt][3] *= sc1;
        }
        __syncwarp();

        // O += P @ V   (A = warp-local P rows; B = V^T rows d)
#pragma unroll
        for (int ks = 0; ks < 4; ks++) {
            int kc = ks << 4;
            uint32_t af[4], bp[4][4];
            ldsm_x4h(af, Ps + ((w << 4) + a_row) * kStrideH + kc + a_col);
#pragma unroll
            for (int p = 0; p < 4; p++)
                ldsm_x4h(bp[p], Vs + ((p << 4) + b_row) * kStrideH + kc + b_col);
#pragma unroll
            for (int dt = 0; dt < 8; dt++)
                mma16(oacc[dt], af, &bp[dt >> 1][(dt & 1) << 1]);
        }
        __syncthreads();   // buffer consumed by all warps before overwrite
    }

    float inv0 = 1.0f / lh[0], inv1 = 1.0f / lh[1];
    __half* o1 = out + (rowbase + i0 + r0l) * kD + h * 64;
    __half* o2 = out + (rowbase + i0 + r0l + 8) * kD + h * 64;
#pragma unroll
    for (int dt = 0; dt < 8; dt++) {
        int dc = (dt << 3) + (quad << 1);
        *(__half2*)(o1 + dc) = __floats2half2_rn(oacc[dt][0] * inv0, oacc[dt][1] * inv0);
        *(__half2*)(o2 + dc) = __floats2half2_rn(oacc[dt][2] * inv1, oacc[dt][3] * inv1);
    }
}

// ---------------- LN(x + t_half): writes fp32 + half copies ----------------
__global__ __launch_bounds__(256) void ln_residual_dual(
    const float* __restrict__ a, const __half* __restrict__ r,
    const float* __restrict__ g, const float* __restrict__ bet,
    float* __restrict__ outf, __half* __restrict__ outh)
{
    const size_t row = (size_t)blockIdx.x * 8 + (threadIdx.x >> 5);
    const int lane = threadIdx.x & 31;
    const float* ap = a + row * kD;
    const __half* rp = r + row * kD;
    float v[16];
    float sum = 0.0f;
#pragma unroll
    for (int t = 0; t < 8; t++) {
        int c = (lane << 1) + (t << 6);
        float2 a2 = *(const float2*)(ap + c);
        float2 r2 = __half22float2(*(const __half2*)(rp + c));
        v[2 * t] = a2.x + r2.x;
        v[2 * t + 1] = a2.y + r2.y;
        sum += v[2 * t] + v[2 * t + 1];
    }
#pragma unroll
    for (int s = 16; s; s >>= 1) sum += __shfl_xor_sync(0xffffffffu, sum, s);
    float mean = sum * (1.0f / kD);
    float s2 = 0.0f;
#pragma unroll
    for (int t = 0; t < 16; t++) { float d = v[t] - mean; s2 += d * d; }
#pragma unroll
    for (int s = 16; s; s >>= 1) s2 += __shfl_xor_sync(0xffffffffu, s2, s);
    float rstd = rsqrtf(s2 * (1.0f / kD) + 1e-5f);
#pragma unroll
    for (int t = 0; t < 8; t++) {
        int c = (lane << 1) + (t << 6);
        float o0 = (v[2 * t] - mean) * rstd * g[c] + bet[c];
        float o1 = (v[2 * t + 1] - mean) * rstd * g[c + 1] + bet[c + 1];
        *(float2*)(outf + row * kD + c) = make_float2(o0, o1);
        *(__half2*)(outh + row * kD + c) = __floats2half2_rn(o0, o1);
    }
}

// ---------------- final logits (fp32) ----------------
__global__ __launch_bounds__(256) void logits_kernel(
    const float* __restrict__ x, const float* __restrict__ w,
    float* __restrict__ out)
{
    int gw = (blockIdx.x * blockDim.x + threadIdx.x) >> 5;
    int lane = threadIdx.x & 31;
    if (gw >= kB * kVOCAB) return;
    int b = gw >> 10;
    int vcb = gw & (kVOCAB - 1);
    const float* xr = x + ((size_t)b * kS + (kS - 1)) * kD;
    const float* wr = w + (size_t)vcb * kD;
    float s = 0.0f;
#pragma unroll
    for (int t = 0; t < 16; t++) s += xr[lane + t * 32] * wr[lane + t * 32];
#pragma unroll
    for (int sh = 16; sh; sh >>= 1) s += __shfl_xor_sync(0xffffffffu, s, sh);
    if (lane == 0) out[gw] = s;
}

// ---------------- host launcher ----------------
extern "C" void kernel_launch(void* const* d_in, const int* in_sizes, int n_in,
                              void* d_out, int out_size)
{
    (void)in_sizes; (void)n_in; (void)out_size;
    const int*   raw_x = (const int*)d_in[0];
    const int*   deg   = (const int*)d_in[1];
    const int*   pci   = (const int*)d_in[2];
    const int*   pcn   = (const int*)d_in[3];
    const int*   sbi   = (const int*)d_in[4];
    const int*   sbn   = (const int*)d_in[5];
    const float* vemb  = (const float*)d_in[6];
    const float* demb  = (const float*)d_in[7];
    const float* are   = (const float*)d_in[8];
    const float* rel   = (const float*)d_in[9];
    const float* Wq    = (const float*)d_in[10];
    const float* bq    = (const float*)d_in[11];
    const float* Wk    = (const float*)d_in[12];
    const float* bk    = (const float*)d_in[13];
    const float* Wv    = (const float*)d_in[14];
    const float* bv    = (const float*)d_in[15];
    const float* Wo    = (const float*)d_in[16];
    const float* bo    = (const float*)d_in[17];
    const float* W1    = (const float*)d_in[18];
    const float* b1    = (const float*)d_in[19];
    const float* W2    = (const float*)d_in[20];
    const float* b2    = (const float*)d_in[21];
    const float* lng   = (const float*)d_in[22];
    const float* lnb   = (const float*)d_in[23];
    const float* logw  = (const float*)d_in[24];
    float* out = (float*)d_out;

    float *x, *bias, *bqkv;
    __half *xh, *qkvh, *vth, *atth, *th, *ffh, *biash, *wqkvh, *woh, *w1h, *w2h;
    cudaGetSymbolAddress((void**)&x,     g_x);
    cudaGetSymbolAddress((void**)&xh,    g_xh);
    cudaGetSymbolAddress((void**)&qkvh,  g_qkvh);
    cudaGetSymbolAddress((void**)&vth,   g_vth);
    cudaGetSymbolAddress((void**)&atth,  g_atth);
    cudaGetSymbolAddress((void**)&th,    g_th);
    cudaGetSymbolAddress((void**)&ffh,   g_ffh);
    cudaGetSymbolAddress((void**)&bias,  g_bias);
    cudaGetSymbolAddress((void**)&biash, g_biash);
    cudaGetSymbolAddress((void**)&wqkvh, g_wqkvh);
    cudaGetSymbolAddress((void**)&bqkv,  g_bqkv);
    cudaGetSymbolAddress((void**)&woh,   g_woh);
    cudaGetSymbolAddress((void**)&w1h,   g_w1h);
    cudaGetSymbolAddress((void**)&w2h,   g_w2h);

    cudaFuncSetAttribute(gemm_fp16<false, 2>, cudaFuncAttributeMaxDynamicSharedMemorySize, kGemmSmemBytes);
    cudaFuncSetAttribute(gemm_fp16<false, 0>, cudaFuncAttributeMaxDynamicSharedMemorySize, kGemmSmemBytes);
    cudaFuncSetAttribute(gemm_fp16<true, 1>,  cudaFuncAttributeMaxDynamicSharedMemorySize, kGemmSmemBytes);
    cudaFuncSetAttribute(flash_attn,          cudaFuncAttributeMaxDynamicSharedMemorySize, kFlashSmemBytes);

    const dim3 gQKV(kQKVN / 128, kM / 128);  // (12, 64)
    const dim3 gD(kD / 128, kM / 128);       // (4, 64)
    const dim3 gFF(kDFF / 128, kM / 128);    // (16, 64)
    const dim3 gFl(kS / 128, kB * kH);       // (4, 128)

    embed_kernel<<<kM, 128>>>(raw_x, deg, vemb, demb, x);
    relnow_kernel<<<(kB * kD + 255) / 256, 256>>>(pcn, sbn, are, x);
    half_copy<<<2048, 256>>>(x, xh, (size_t)kM * kD);
    prep_qkv_w<<<2048, 256>>>(Wq, Wk, Wv, wqkvh);
    prep_qkv_b<<<(kL * kQKVN + 255) / 256, 256>>>(bq, bk, bv, bqkv);
    gemm_fp16<false, 2><<<gQKV, 256, kGemmSmemBytes>>>(
        xh, wqkvh, bqkv, qkvh, vth, kM, kQKVN, kD);

    half_copy<<<2048, 256>>>(Wo, woh, (size_t)kL * kD * kD);
    half_copy<<<2048, 256>>>(W1, w1h, (size_t)kL * kDFF * kD);
    half_copy<<<2048, 256>>>(W2, w2h, (size_t)kL * kD * kDFF);
    zero_bias<<<2048, 256>>>(bias);
    scatter_pc<<<(kNPC + 255) / 256, 256>>>(pci, rel, bias);
    scatter_sib<<<(kNS + 255) / 256, 256>>>(sbi, rel, bias);
    half_copy<<<2048, 256>>>(bias, biash, (size_t)kB * kS * kS);

    for (int l = 0; l < kL; l++) {
        const __half* wqkvl = wqkvh + (size_t)l * kQKVN * kD;
        const float*  bqkvl = bqkv + (size_t)l * kQKVN;
        const __half* wol = woh + (size_t)l * kD * kD;
        const __half* w1l = w1h + (size_t)l * kDFF * kD;
        const __half* w2l = w2h + (size_t)l * kD * kDFF;
        const float* bol = bo + (size_t)l * kD;
        const float* b1l = b1 + (size_t)l * kDFF;
        const float* b2l = b2 + (size_t)l * kD;
        const float* lngl = lng + (size_t)l * kD;
        const float* lnbl = lnb + (size_t)l * kD;

        if (l > 0) {
            gemm_fp16<false, 2><<<gQKV, 256, kGemmSmemBytes>>>(
                xh, wqkvl, bqkvl, qkvh, vth, kM, kQKVN, kD);
        }
        flash_attn<<<gFl, 256, kFlashSmemBytes>>>(qkvh, vth, biash, atth);
        gemm_fp16<false, 0><<<gD, 256, kGemmSmemBytes>>>(
            atth, wol, bol, th, nullptr, kM, kD, kD);
        ln_residual_dual<<<kM / 8, 256>>>(x, th, lngl, lnbl, x, xh);

        gemm_fp16<true, 1><<<gFF, 256, kGemmSmemBytes>>>(
            xh, w1l, b1l, ffh, nullptr, kM, kDFF, kD);
        gemm_fp16<false, 0><<<gD, 256, kGemmSmemBytes>>>(
            ffh, w2l, b2l, th, nullptr, kM, kD, kDFF);
        ln_residual_dual<<<kM / 8, 256>>>(x, th, lngl, lnbl, x, xh);
    }

    logits_kernel<<<(kB * kVOCAB * 32 + 255) / 256, 256>>>(x, logw, out);
}

// round 11
// speedup vs baseline: 1.0777x; 1.0100x over previous
#include <cuda_runtime.h>
#include <cuda_fp16.h>
#include <math.h>
#include <stdint.h>

// ---------------- problem constants ----------------
constexpr int kB = 16;
constexpr int kS = 512;
constexpr int kD = 512;
constexpr int kH = 8;
constexpr int kL = 6;
constexpr int kDFF = 2048;
constexpr int kVOCAB = 1024;
constexpr int kNPC = 4096;
constexpr int kNS = 4096;
constexpr int kM = kB * kS;  // 8192 rows
constexpr int kQKVN = 3 * kD; // 1536

// ---------------- scratch (static device globals; no allocations) ----------------
__device__ float  g_x[(size_t)kM * kD];        // residual stream (fp32)
__device__ __half g_xh[(size_t)kM * kD];       // half copy for GEMM input
__device__ __half g_qkvh[(size_t)kM * 1024];   // Q (0-511) and K (512-1023), half
__device__ __half g_vth[(size_t)kM * kD];      // V transposed: [b][h*64+d][s], half
__device__ __half g_atth[(size_t)kM * kD];     // attention output, half
__device__ __half g_th[(size_t)kM * kD];       // pre-LN branch (half)
__device__ __half g_ffh[(size_t)kM * kDFF];    // FFN hidden, half
__device__ __half g_biash[(size_t)kB * kS * kS];// dense relation bias (half)
__device__ __half g_wqkvh[(size_t)kL * kQKVN * kD];
__device__ float  g_bqkv[(size_t)kL * kQKVN];
__device__ __half g_woh[(size_t)kL * kD * kD];
__device__ __half g_w1h[(size_t)kL * kDFF * kD];
__device__ __half g_w2h[(size_t)kL * kD * kDFF];

// ---------------- mma / ldmatrix / cp.async helpers ----------------
__device__ __forceinline__ void mma16(float* c, const uint32_t* a, const uint32_t* b) {
    asm volatile(
        "mma.sync.aligned.m16n8k16.row.col.f32.f16.f16.f32 "
        "{%0,%1,%2,%3},{%4,%5,%6,%7},{%8,%9},{%0,%1,%2,%3};"
        : "+f"(c[0]), "+f"(c[1]), "+f"(c[2]), "+f"(c[3])
        : "r"(a[0]), "r"(a[1]), "r"(a[2]), "r"(a[3]), "r"(b[0]), "r"(b[1]));
}

__device__ __forceinline__ void ldsm_x4h(uint32_t* r, const __half* p) {
    uint32_t addr = (uint32_t)__cvta_generic_to_shared(p);
    asm volatile("ldmatrix.sync.aligned.m8n8.x4.shared.b16 {%0,%1,%2,%3}, [%4];"
        : "=r"(r[0]), "=r"(r[1]), "=r"(r[2]), "=r"(r[3]) : "r"(addr));
}

__device__ __forceinline__ void cpa16(void* smem_dst, const void* gsrc) {
    uint32_t sa = (uint32_t)__cvta_generic_to_shared(smem_dst);
    asm volatile("cp.async.cg.shared.global [%0], [%1], 16;" :: "r"(sa), "l"(gsrc) : "memory");
}
__device__ __forceinline__ void cpa_commit() {
    asm volatile("cp.async.commit_group;" ::: "memory");
}
__device__ __forceinline__ void cpa_wait0() {
    asm volatile("cp.async.wait_group 0;" ::: "memory");
}
__device__ __forceinline__ void cpa_wait1() {
    asm volatile("cp.async.wait_group 1;" ::: "memory");
}

// ---------------- prep kernels ----------------
__global__ __launch_bounds__(256) void prep_qkv_w(
    const float* __restrict__ Wq, const float* __restrict__ Wk,
    const float* __restrict__ Wv, __half* __restrict__ wout)
{
    size_t n = (size_t)kL * kQKVN * kD;
    for (size_t idx = (size_t)blockIdx.x * blockDim.x + threadIdx.x; idx < n;
         idx += (size_t)gridDim.x * blockDim.x) {
        size_t l = idx / ((size_t)kQKVN * kD);
        size_t rem = idx % ((size_t)kQKVN * kD);
        int r = (int)(rem / kD), c = (int)(rem % kD);
        float v;
        if (r < kD)            v = Wq[(l * kD + r) * kD + c];
        else if (r < 2 * kD)   v = Wk[(l * kD + (r - kD)) * kD + c];
        else                   v = Wv[(l * kD + (r - 2 * kD)) * kD + c];
        wout[idx] = __float2half_rn(v);
    }
}

__global__ __launch_bounds__(256) void prep_qkv_b(
    const float* __restrict__ bq, const float* __restrict__ bk,
    const float* __restrict__ bv, float* __restrict__ bout)
{
    int idx = blockIdx.x * blockDim.x + threadIdx.x;
    if (idx >= kL * kQKVN) return;
    int l = idx / kQKVN, r = idx % kQKVN;
    float v;
    if (r < kD)          v = bq[l * kD + r];
    else if (r < 2 * kD) v = bk[l * kD + (r - kD)];
    else                 v = bv[l * kD + (r - 2 * kD)];
    bout[idx] = v;
}

__global__ __launch_bounds__(256) void half_copy(
    const float* __restrict__ src, __half* __restrict__ dst, size_t n)
{
    for (size_t i = (size_t)blockIdx.x * blockDim.x + threadIdx.x; i < n;
         i += (size_t)gridDim.x * blockDim.x)
        dst[i] = __float2half_rn(src[i]);
}

// ---------------- dense relation-bias matrix (half) ----------------
__global__ __launch_bounds__(256) void zero_bias_h(__half* __restrict__ bias)
{
    size_t n = (size_t)kB * kS * kS / 2;   // half2 count
    uint32_t* p = (uint32_t*)bias;
    for (size_t i = (size_t)blockIdx.x * blockDim.x + threadIdx.x; i < n;
         i += (size_t)gridDim.x * blockDim.x)
        p[i] = 0u;
}

__global__ __launch_bounds__(256) void scatter_pc_h(
    const int* __restrict__ pci, const float* __restrict__ rel, __half* __restrict__ bias)
{
    int e = blockIdx.x * blockDim.x + threadIdx.x;
    if (e >= kNPC) return;
    int b = pci[e * 3 + 0], i = pci[e * 3 + 1], j = pci[e * 3 + 2];
    atomicAdd(&bias[((size_t)b * kS + i) * kS + j], __float2half(rel[0]));
    atomicAdd(&bias[((size_t)b * kS + j) * kS + i], __float2half(rel[1]));
}

__global__ __launch_bounds__(256) void scatter_sib_h(
    const int* __restrict__ sbi, const float* __restrict__ rel, __half* __restrict__ bias)
{
    int e = blockIdx.x * blockDim.x + threadIdx.x;
    if (e >= kNS) return;
    int b = sbi[e * 3 + 0], i = sbi[e * 3 + 1], j = sbi[e * 3 + 2];
    __half r2 = __float2half(rel[2]);
    atomicAdd(&bias[((size_t)b * kS + i) * kS + j], r2);
    atomicAdd(&bias[((size_t)b * kS + j) * kS + i], r2);
}

// ---------------- embedding + positional + degree ----------------
__global__ __launch_bounds__(128) void embed_kernel(
    const int* __restrict__ raw_x, const int* __restrict__ deg,
    const float* __restrict__ vemb, const float* __restrict__ demb,
    float* __restrict__ x)
{
    const int row = blockIdx.x;
    const int s = row & (kS - 1);
    const int tok = raw_x[row];
    const int dg = deg[row];
    const float c0 = -logf(10000.0f) / (float)kD;
    for (int c = threadIdx.x; c < kD; c += blockDim.x) {
        int p = c >> 1;
        float ang = (float)s * expf((float)(2 * p) * c0);
        float pe = (c & 1) ? cosf(ang) : sinf(ang);
        x[(size_t)row * kD + c] = vemb[(size_t)tok * kD + c] + pe + demb[(size_t)dg * kD + c];
    }
}

__global__ __launch_bounds__(256) void relnow_kernel(
    const int* __restrict__ pcn, const int* __restrict__ sn,
    const float* __restrict__ are, float* __restrict__ x)
{
    int idx = blockIdx.x * blockDim.x + threadIdx.x;
    if (idx >= kB * kD) return;
    int b = idx / kD, c = idx % kD;
    {
        int bb = pcn[b * 2 + 0], ss = pcn[b * 2 + 1];
        atomicAdd(&x[((size_t)bb * kS + ss) * kD + c], are[c]);
    }
    {
        int bb = sn[b * 2 + 0], ss = sn[b * 2 + 1];
        atomicAdd(&x[((size_t)bb * kS + ss) * kD + c], are[kD + c]);
    }
}

// ============================================================
// fp16 tensor-core GEMM, 3-stage cp.async pipeline.
// acc(fp32) = A[M,K](half) @ W[N,K]^T(half) + bias(fp32)
// MODE 0: half out Ch (no relu).  MODE 1: half out Ch + relu.
// MODE 2: QKV — Q,K tiles (n0<1024) to Ch stride 1024; V tiles
//         (n0>=1024) transposed into vt[b][hd][s] (half).
// 128x128 tile, 8 warps (64x32), BK=64 halfs, smem stride 72.
// ============================================================
constexpr int kStrideH = 72;
constexpr int kStageH = 2 * 128 * kStrideH;            // halfs per stage (A+B)
constexpr int kGemmSmemBytes = 3 * kStageH * 2;        // 110,592 B

template <bool RELU, int MODE>
__global__ __launch_bounds__(256, 2) void gemm_fp16(
    const __half* __restrict__ A, const __half* __restrict__ W,
    const float* __restrict__ bias, __half* __restrict__ Ch,
    __half* __restrict__ vt, int M, int N, int K)
{
    extern __shared__ __half smh[];
    const int tid = threadIdx.x;
    const int lane = tid & 31, warp = tid >> 5;
    const int wm = warp >> 2, wn = warp & 3;
    const int m0 = blockIdx.y << 7, n0 = blockIdx.x << 7;

    // fragment lane addressing
    const int a_row = (((lane >> 3) & 1) << 3) + (lane & 7);
    const int a_col = (lane >> 4) << 3;
    const int b_row = ((lane >> 4) << 3) + (lane & 7);
    const int b_col = ((lane >> 3) & 1) << 3;

    auto issue = [&](int ch, int st) {
        const __half* Ab = A + (size_t)m0 * K + (size_t)ch * 64;
        const __half* Wb = W + (size_t)n0 * K + (size_t)ch * 64;
        __half* Ad = smh + st * kStageH;
        __half* Bd = Ad + (kStageH >> 1);
#pragma unroll
        for (int it = 0; it < 4; it++) {
            int u = tid + (it << 8);       // 0..1023
            int row = u >> 3, c8 = (u & 7) << 3;
            cpa16(Ad + row * kStrideH + c8, Ab + (size_t)row * K + c8);
            cpa16(Bd + row * kStrideH + c8, Wb + (size_t)row * K + c8);
        }
        cpa_commit();
    };

    float acc[4][4][4] = {};
    const int nch = K >> 6;
    issue(0, 0);
    issue(1, 1);
    int st = 0, st2 = 2;
    for (int ch = 0; ch < nch; ch++) {
        if (ch + 1 < nch) cpa_wait1(); else cpa_wait0();
        __syncthreads();
        if (ch + 2 < nch) issue(ch + 2, st2);
        const __half* Ar = smh + st * kStageH;
        const __half* Br = Ar + (kStageH >> 1);
#pragma unroll
        for (int ks = 0; ks < 4; ks++) {
            int kc = ks << 4;
            uint32_t af[4][4], bp[2][4];
#pragma unroll
            for (int mt = 0; mt < 4; mt++)
                ldsm_x4h(af[mt], Ar + ((wm << 6) + (mt << 4) + a_row) * kStrideH + kc + a_col);
#pragma unroll
            for (int p = 0; p < 2; p++)
                ldsm_x4h(bp[p], Br + ((wn << 5) + (p << 4) + b_row) * kStrideH + kc + b_col);
#pragma unroll
            for (int mt = 0; mt < 4; mt++)
#pragma unroll
                for (int nt = 0; nt < 4; nt++)
                    mma16(acc[mt][nt], af[mt], &bp[nt >> 1][(nt & 1) << 1]);
        }
        st = (st == 2) ? 0 : st + 1;
        st2 = (st2 == 2) ? 0 : st2 + 1;
    }

    if (MODE == 2 && n0 >= 1024) {
        // V tile -> vt[b][hd][s] transposed (half)
        const int bidx = m0 >> 9;
        __half* vtb = vt + ((size_t)bidx << 9) * kS;
#pragma unroll
        for (int mt = 0; mt < 4; mt++) {
            int s = (m0 & 511) + (wm << 6) + (mt << 4) + (lane >> 2);
#pragma unroll
            for (int nt = 0; nt < 4; nt++) {
                int col = n0 + (wn << 5) + (nt << 3) + ((lane & 3) << 1);
                int hd = col - 1024;
                float bb0 = bias[col], bb1 = bias[col + 1];
                vtb[(size_t)hd * kS + s]           = __float2half_rn(acc[mt][nt][0] + bb0);
                vtb[(size_t)(hd + 1) * kS + s]     = __float2half_rn(acc[mt][nt][1] + bb1);
                vtb[(size_t)hd * kS + s + 8]       = __float2half_rn(acc[mt][nt][2] + bb0);
                vtb[(size_t)(hd + 1) * kS + s + 8] = __float2half_rn(acc[mt][nt][3] + bb1);
            }
        }
        return;
    }
#pragma unroll
    for (int mt = 0; mt < 4; mt++) {
        int row = m0 + (wm << 6) + (mt << 4) + (lane >> 2);
#pragma unroll
        for (int nt = 0; nt < 4; nt++) {
            int col = n0 + (wn << 5) + (nt << 3) + ((lane & 3) << 1);
            float bb0 = bias[col], bb1 = bias[col + 1];
            float v0 = acc[mt][nt][0] + bb0, v1 = acc[mt][nt][1] + bb1;
            float v2 = acc[mt][nt][2] + bb0, v3 = acc[mt][nt][3] + bb1;
            if (RELU) {
                v0 = fmaxf(v0, 0.0f); v1 = fmaxf(v1, 0.0f);
                v2 = fmaxf(v2, 0.0f); v3 = fmaxf(v3, 0.0f);
            }
            if (MODE == 2) {
                // Q/K tile: stride 1024
                *(__half2*)(Ch + (size_t)row * 1024 + col) = __floats2half2_rn(v0, v1);
                *(__half2*)(Ch + (size_t)(row + 8) * 1024 + col) = __floats2half2_rn(v2, v3);
            } else {
                *(__half2*)(Ch + (size_t)row * N + col) = __floats2half2_rn(v0, v1);
                *(__half2*)(Ch + (size_t)(row + 8) * N + col) = __floats2half2_rn(v2, v3);
            }
        }
    }
}

// ============================================================
// Fused fp16 flash attention, double-buffered K/V, half bias,
// register-resident P (C-fragment == A-fragment layout identity).
// Q,K from qkvh [kM][1024]; V from vth [b][h*64+d][s].
// ============================================================
constexpr int kQsOff = 0;                         // [128][72]
constexpr int kKsOff = 128 * kStrideH;            // [2][64][72]
constexpr int kVsOff = kKsOff + 2 * 64 * kStrideH;// [2][64][72]
constexpr int kFlashSmemH = kVsOff + 2 * 64 * kStrideH;
constexpr int kFlashSmemBytes = kFlashSmemH * 2;  // 55,296 B

__global__ __launch_bounds__(256, 2) void flash_attn(
    const __half* __restrict__ qkv, const __half* __restrict__ vt,
    const __half* __restrict__ bias, __half* __restrict__ out)
{
    extern __shared__ __half smh[];
    __half* Qs = smh + kQsOff;
    const int bh = blockIdx.y;
    const int b = bh >> 3, h = bh & 7;
    const int i0 = blockIdx.x << 7;
    const int tid = threadIdx.x;
    const int lane = tid & 31, w = tid >> 5;
    const int quad = lane & 3;
    const int r0l = (w << 4) + (lane >> 2);
    const size_t rowbase = (size_t)b * kS;

    const int a_row = (((lane >> 3) & 1) << 3) + (lane & 7);
    const int a_col = (lane >> 4) << 3;
    const int b_row = ((lane >> 4) << 3) + (lane & 7);
    const int b_col = ((lane >> 3) & 1) << 3;

    const __half* Vgb = vt + ((rowbase << 9) + (size_t)h * 64 * kS);

    auto issueKV = [&](int jt, int buf) {
        const int j0 = jt << 6;
        __half* Ks = smh + kKsOff + buf * 64 * kStrideH;
        __half* Vs = smh + kVsOff + buf * 64 * kStrideH;
        const __half* Kg = qkv + (rowbase + j0) * 1024 + 512 + h * 64;
#pragma unroll
        for (int it = 0; it < 2; it++) {
            int u = tid + (it << 8);
            int row = u >> 3, c8 = (u & 7) << 3;
            cpa16(Ks + row * kStrideH + c8, Kg + (size_t)row * 1024 + c8);
            cpa16(Vs + row * kStrideH + c8, Vgb + (size_t)row * kS + j0 + c8);
        }
        cpa_commit();
    };

    // load Q tile (128 x 64 halfs), then first K/V
    {
        const __half* Qg = qkv + (rowbase + i0) * 1024 + h * 64;
#pragma unroll
        for (int it = 0; it < 4; it++) {
            int u = tid + (it << 8);
            int row = u >> 3, c8 = (u & 7) << 3;
            cpa16(Qs + row * kStrideH + c8, Qg + (size_t)row * 1024 + c8);
        }
        cpa_commit();
    }
    issueKV(0, 0);

    float oacc[8][4] = {};
    float mh[2] = {-1e30f, -1e30f};
    float lh[2] = {0.0f, 0.0f};

    for (int jt = 0; jt < 8; jt++) {
        const int j0 = jt << 6;
        const int buf = jt & 1;
        if (jt + 1 < 8) { issueKV(jt + 1, buf ^ 1); cpa_wait1(); }
        else            { cpa_wait0(); }
        __syncthreads();
        const __half* Ks = smh + kKsOff + buf * 64 * kStrideH;
        const __half* Vs = smh + kVsOff + buf * 64 * kStrideH;

        // S = Q @ K^T   (warp: 16 rows x 64 j)
        float s[8][4] = {};
#pragma unroll
        for (int ks = 0; ks < 4; ks++) {
            int kc = ks << 4;
            uint32_t af[4], bp[4][4];
            ldsm_x4h(af, Qs + ((w << 4) + a_row) * kStrideH + kc + a_col);
#pragma unroll
            for (int p = 0; p < 4; p++)
                ldsm_x4h(bp[p], Ks + ((p << 4) + b_row) * kStrideH + kc + b_col);
#pragma unroll
            for (int nt = 0; nt < 8; nt++)
                mma16(s[nt], af, &bp[nt >> 1][(nt & 1) << 1]);
        }

        const size_t bi1 = (rowbase + i0 + r0l) * kS + j0;
        const size_t bi2 = (rowbase + i0 + r0l + 8) * kS + j0;
#pragma unroll
        for (int nt = 0; nt < 8; nt++) {
            int jc = (nt << 3) + (quad << 1);
            float2 z1 = __half22float2(*(const __half2*)(bias + bi1 + jc));
            float2 z2 = __half22float2(*(const __half2*)(bias + bi2 + jc));
            s[nt][0] = s[nt][0] * 0.125f + z1.x;
            s[nt][1] = s[nt][1] * 0.125f + z1.y;
            s[nt][2] = s[nt][2] * 0.125f + z2.x;
            s[nt][3] = s[nt][3] * 0.125f + z2.y;
        }
        float mx0 = -1e30f, mx1 = -1e30f;
#pragma unroll
        for (int nt = 0; nt < 8; nt++) {
            mx0 = fmaxf(mx0, fmaxf(s[nt][0], s[nt][1]));
            mx1 = fmaxf(mx1, fmaxf(s[nt][2], s[nt][3]));
        }
        mx0 = fmaxf(mx0, __shfl_xor_sync(0xffffffffu, mx0, 1));
        mx0 = fmaxf(mx0, __shfl_xor_sync(0xffffffffu, mx0, 2));
        mx1 = fmaxf(mx1, __shfl_xor_sync(0xffffffffu, mx1, 1));
        mx1 = fmaxf(mx1, __shfl_xor_sync(0xffffffffu, mx1, 2));
        float mn0 = fmaxf(mh[0], mx0), mn1 = fmaxf(mh[1], mx1);
        float sc0 = __expf(mh[0] - mn0), sc1 = __expf(mh[1] - mn1);
        mh[0] = mn0; mh[1] = mn1;

        // exp + convert straight into A-fragments (C-frag == A-frag layout)
        uint32_t pfrag[4][4];
        float ps0 = 0.0f, ps1 = 0.0f;
#pragma unroll
        for (int nt = 0; nt < 8; nt++) {
            __half2 h1 = __floats2half2_rn(__expf(s[nt][0] - mn0), __expf(s[nt][1] - mn0));
            __half2 h2 = __floats2half2_rn(__expf(s[nt][2] - mn1), __expf(s[nt][3] - mn1));
            float2 f1 = __half22float2(h1);
            float2 f2 = __half22float2(h2);
            ps0 += f1.x + f1.y; ps1 += f2.x + f2.y;
            pfrag[nt >> 1][((nt & 1) << 1) + 0] = *(uint32_t*)&h1;
            pfrag[nt >> 1][((nt & 1) << 1) + 1] = *(uint32_t*)&h2;
        }
        ps0 += __shfl_xor_sync(0xffffffffu, ps0, 1);
        ps0 += __shfl_xor_sync(0xffffffffu, ps0, 2);
        ps1 += __shfl_xor_sync(0xffffffffu, ps1, 1);
        ps1 += __shfl_xor_sync(0xffffffffu, ps1, 2);
        lh[0] = lh[0] * sc0 + ps0;
        lh[1] = lh[1] * sc1 + ps1;
#pragma unroll
        for (int dt = 0; dt < 8; dt++) {
            oacc[dt][0] *= sc0; oacc[dt][1] *= sc0;
            oacc[dt][2] *= sc1; oacc[dt][3] *= sc1;
        }

        // O += P @ V   (A = register pfrag; B = V^T rows d via ldmatrix)
#pragma unroll
        for (int ks = 0; ks < 4; ks++) {
            int kc = ks << 4;
            uint32_t bp[4][4];
#pragma unroll
            for (int p = 0; p < 4; p++)
                ldsm_x4h(bp[p], Vs + ((p << 4) + b_row) * kStrideH + kc + b_col);
#pragma unroll
            for (int dt = 0; dt < 8; dt++)
                mma16(oacc[dt], pfrag[ks], &bp[dt >> 1][(dt & 1) << 1]);
        }
        __syncthreads();   // buffer consumed by all warps before overwrite
    }

    float inv0 = 1.0f / lh[0], inv1 = 1.0f / lh[1];
    __half* o1 = out + (rowbase + i0 + r0l) * kD + h * 64;
    __half* o2 = out + (rowbase + i0 + r0l + 8) * kD + h * 64;
#pragma unroll
    for (int dt = 0; dt < 8; dt++) {
        int dc = (dt << 3) + (quad << 1);
        *(__half2*)(o1 + dc) = __floats2half2_rn(oacc[dt][0] * inv0, oacc[dt][1] * inv0);
        *(__half2*)(o2 + dc) = __floats2half2_rn(oacc[dt][2] * inv1, oacc[dt][3] * inv1);
    }
}

// ---------------- LN(x + t_half): writes fp32 + half copies ----------------
__global__ __launch_bounds__(256) void ln_residual_dual(
    const float* __restrict__ a, const __half* __restrict__ r,
    const float* __restrict__ g, const float* __restrict__ bet,
    float* __restrict__ outf, __half* __restrict__ outh)
{
    const size_t row = (size_t)blockIdx.x * 8 + (threadIdx.x >> 5);
    const int lane = threadIdx.x & 31;
    const float* ap = a + row * kD;
    const __half* rp = r + row * kD;
    float v[16];
    float sum = 0.0f;
#pragma unroll
    for (int t = 0; t < 8; t++) {
        int c = (lane << 1) + (t << 6);
        float2 a2 = *(const float2*)(ap + c);
        float2 r2 = __half22float2(*(const __half2*)(rp + c));
        v[2 * t] = a2.x + r2.x;
        v[2 * t + 1] = a2.y + r2.y;
        sum += v[2 * t] + v[2 * t + 1];
    }
#pragma unroll
    for (int s = 16; s; s >>= 1) sum += __shfl_xor_sync(0xffffffffu, sum, s);
    float mean = sum * (1.0f / kD);
    float s2 = 0.0f;
#pragma unroll
    for (int t = 0; t < 16; t++) { float d = v[t] - mean; s2 += d * d; }
#pragma unroll
    for (int s = 16; s; s >>= 1) s2 += __shfl_xor_sync(0xffffffffu, s2, s);
    float rstd = rsqrtf(s2 * (1.0f / kD) + 1e-5f);
#pragma unroll
    for (int t = 0; t < 8; t++) {
        int c = (lane << 1) + (t << 6);
        float o0 = (v[2 * t] - mean) * rstd * g[c] + bet[c];
        float o1 = (v[2 * t + 1] - mean) * rstd * g[c + 1] + bet[c + 1];
        *(float2*)(outf + row * kD + c) = make_float2(o0, o1);
        *(__half2*)(outh + row * kD + c) = __floats2half2_rn(o0, o1);
    }
}

// ---------------- final logits (fp32) ----------------
__global__ __launch_bounds__(256) void logits_kernel(
    const float* __restrict__ x, const float* __restrict__ w,
    float* __restrict__ out)
{
    int gw = (blockIdx.x * blockDim.x + threadIdx.x) >> 5;
    int lane = threadIdx.x & 31;
    if (gw >= kB * kVOCAB) return;
    int b = gw >> 10;
    int vcb = gw & (kVOCAB - 1);
    const float* xr = x + ((size_t)b * kS + (kS - 1)) * kD;
    const float* wr = w + (size_t)vcb * kD;
    float s = 0.0f;
#pragma unroll
    for (int t = 0; t < 16; t++) s += xr[lane + t * 32] * wr[lane + t * 32];
#pragma unroll
    for (int sh = 16; sh; sh >>= 1) s += __shfl_xor_sync(0xffffffffu, s, sh);
    if (lane == 0) out[gw] = s;
}

// ---------------- host launcher ----------------
extern "C" void kernel_launch(void* const* d_in, const int* in_sizes, int n_in,
                              void* d_out, int out_size)
{
    (void)in_sizes; (void)n_in; (void)out_size;
    const int*   raw_x = (const int*)d_in[0];
    const int*   deg   = (const int*)d_in[1];
    const int*   pci   = (const int*)d_in[2];
    const int*   pcn   = (const int*)d_in[3];
    const int*   sbi   = (const int*)d_in[4];
    const int*   sbn   = (const int*)d_in[5];
    const float* vemb  = (const float*)d_in[6];
    const float* demb  = (const float*)d_in[7];
    const float* are   = (const float*)d_in[8];
    const float* rel   = (const float*)d_in[9];
    const float* Wq    = (const float*)d_in[10];
    const float* bq    = (const float*)d_in[11];
    const float* Wk    = (const float*)d_in[12];
    const float* bk    = (const float*)d_in[13];
    const float* Wv    = (const float*)d_in[14];
    const float* bv    = (const float*)d_in[15];
    const float* Wo    = (const float*)d_in[16];
    const float* bo    = (const float*)d_in[17];
    const float* W1    = (const float*)d_in[18];
    const float* b1    = (const float*)d_in[19];
    const float* W2    = (const float*)d_in[20];
    const float* b2    = (const float*)d_in[21];
    const float* lng   = (const float*)d_in[22];
    const float* lnb   = (const float*)d_in[23];
    const float* logw  = (const float*)d_in[24];
    float* out = (float*)d_out;

    float *x, *bqkv;
    __half *xh, *qkvh, *vth, *atth, *th, *ffh, *biash, *wqkvh, *woh, *w1h, *w2h;
    cudaGetSymbolAddress((void**)&x,     g_x);
    cudaGetSymbolAddress((void**)&xh,    g_xh);
    cudaGetSymbolAddress((void**)&qkvh,  g_qkvh);
    cudaGetSymbolAddress((void**)&vth,   g_vth);
    cudaGetSymbolAddress((void**)&atth,  g_atth);
    cudaGetSymbolAddress((void**)&th,    g_th);
    cudaGetSymbolAddress((void**)&ffh,   g_ffh);
    cudaGetSymbolAddress((void**)&biash, g_biash);
    cudaGetSymbolAddress((void**)&wqkvh, g_wqkvh);
    cudaGetSymbolAddress((void**)&bqkv,  g_bqkv);
    cudaGetSymbolAddress((void**)&woh,   g_woh);
    cudaGetSymbolAddress((void**)&w1h,   g_w1h);
    cudaGetSymbolAddress((void**)&w2h,   g_w2h);

    cudaFuncSetAttribute(gemm_fp16<false, 2>, cudaFuncAttributeMaxDynamicSharedMemorySize, kGemmSmemBytes);
    cudaFuncSetAttribute(gemm_fp16<false, 0>, cudaFuncAttributeMaxDynamicSharedMemorySize, kGemmSmemBytes);
    cudaFuncSetAttribute(gemm_fp16<true, 1>,  cudaFuncAttributeMaxDynamicSharedMemorySize, kGemmSmemBytes);
    cudaFuncSetAttribute(flash_attn,          cudaFuncAttributeMaxDynamicSharedMemorySize, kFlashSmemBytes);

    const dim3 gQKV(kQKVN / 128, kM / 128);  // (12, 64)
    const dim3 gD(kD / 128, kM / 128);       // (4, 64)
    const dim3 gFF(kDFF / 128, kM / 128);    // (16, 64)
    const dim3 gFl(kS / 128, kB * kH);       // (4, 128)

    embed_kernel<<<kM, 128>>>(raw_x, deg, vemb, demb, x);
    relnow_kernel<<<(kB * kD + 255) / 256, 256>>>(pcn, sbn, are, x);
    half_copy<<<2048, 256>>>(x, xh, (size_t)kM * kD);
    prep_qkv_w<<<2048, 256>>>(Wq, Wk, Wv, wqkvh);
    prep_qkv_b<<<(kL * kQKVN + 255) / 256, 256>>>(bq, bk, bv, bqkv);
    gemm_fp16<false, 2><<<gQKV, 256, kGemmSmemBytes>>>(
        xh, wqkvh, bqkv, qkvh, vth, kM, kQKVN, kD);

    half_copy<<<2048, 256>>>(Wo, woh, (size_t)kL * kD * kD);
    half_copy<<<2048, 256>>>(W1, w1h, (size_t)kL * kDFF * kD);
    half_copy<<<2048, 256>>>(W2, w2h, (size_t)kL * kD * kDFF);
    zero_bias_h<<<2048, 256>>>(biash);
    scatter_pc_h<<<(kNPC + 255) / 256, 256>>>(pci, rel, biash);
    scatter_sib_h<<<(kNS + 255) / 256, 256>>>(sbi, rel, biash);

    for (int l = 0; l < kL; l++) {
        const __half* wqkvl = wqkvh + (size_t)l * kQKVN * kD;
        const float*  bqkvl = bqkv + (size_t)l * kQKVN;
        const __half* wol = woh + (size_t)l * kD * kD;
        const __half* w1l = w1h + (size_t)l * kDFF * kD;
        const __half* w2l = w2h + (size_t)l * kD * kDFF;
        const float* bol = bo + (size_t)l * kD;
        const float* b1l = b1 + (size_t)l * kDFF;
        const float* b2l = b2 + (size_t)l * kD;
        const float* lngl = lng + (size_t)l * kD;
        const float* lnbl = lnb + (size_t)l * kD;

        if (l > 0) {
            gemm_fp16<false, 2><<<gQKV, 256, kGemmSmemBytes>>>(
                xh, wqkvl, bqkvl, qkvh, vth, kM, kQKVN, kD);
        }
        flash_attn<<<gFl, 256, kFlashSmemBytes>>>(qkvh, vth, biash, atth);
        gemm_fp16<false, 0><<<gD, 256, kGemmSmemBytes>>>(
            atth, wol, bol, th, nullptr, kM, kD, kD);
        ln_residual_dual<<<kM / 8, 256>>>(x, th, lngl, lnbl, x, xh);

        gemm_fp16<true, 1><<<gFF, 256, kGemmSmemBytes>>>(
            xh, w1l, b1l, ffh, nullptr, kM, kDFF, kD);
        gemm_fp16<false, 0><<<gD, 256, kGemmSmemBytes>>>(
            ffh, w2l, b2l, th, nullptr, kM, kD, kDFF);
        ln_residual_dual<<<kM / 8, 256>>>(x, th, lngl, lnbl, x, xh);
    }

    logits_kernel<<<(kB * kVOCAB * 32 + 255) / 256, 256>>>(x, logw, out);
}